// round 12
// baseline (speedup 1.0000x reference)
#include <cuda_runtime.h>
#include <cstdint>
#include <math.h>

#define T_    512
#define H_    1024
#define HD_   64
#define NQ_   16
#define NKV_  4
#define G_    4
#define E_    8
#define FFN_  1024
#define B_    4
#define Q_    128
#define P_    8
#define PS_   128
#define S_    1024
#define SW_   128
#define QKVD  1536
#define SCALE_ 0.125f
#define ALPHA_ 1.702f
#define LIMIT_ 7.0f
#define EPS_   1e-5f
#define NAPAD 2048

#define QKV_SPLIT 2
#define OPJ_SPLIT 4
#define DN_SPLIT  2

// ---------------- scratch ----------------
__device__ float g_x[T_ * H_];
__device__ float g_qkvp[QKV_SPLIT * T_ * QKVD];
__device__ float g_attn[T_ * NQ_ * HD_];
__device__ float g_outp[OPJ_SPLIT * T_ * H_];
__device__ float g_x2[T_ * H_];
__device__ int   g_eidx[T_ * 2];
__device__ float g_ewt[T_ * 2];
__device__ int   g_eoff[E_];
__device__ int   g_ecnt[E_];
__device__ int   g_tokof[NAPAD];
__device__ int   g_slotmap[T_ * 2];
__device__ float g_act[NAPAD * FFN_];
__device__ float g_eop[DN_SPLIT * NAPAD * H_];

// ---------------- helpers ----------------
__device__ __forceinline__ uint32_t f2tf_bits(uint32_t bits) {
    uint32_t r;
    asm("cvt.rna.tf32.f32 %0, %1;" : "=r"(r) : "f"(__uint_as_float(bits)));
    return r;
}
__device__ __forceinline__ float roundtf(float f) {
    uint32_t r;
    asm("cvt.rna.tf32.f32 %0, %1;" : "=r"(r) : "f"(f));
    return __uint_as_float(r);
}
__device__ __forceinline__ void mma8(float* c, uint32_t a0, uint32_t a1,
                                     uint32_t a2, uint32_t a3,
                                     uint32_t b0, uint32_t b1) {
    asm volatile("mma.sync.aligned.m16n8k8.row.col.f32.tf32.tf32.f32 "
        "{%0,%1,%2,%3}, {%4,%5,%6,%7}, {%8,%9}, {%0,%1,%2,%3};"
        : "+f"(c[0]), "+f"(c[1]), "+f"(c[2]), "+f"(c[3])
        : "r"(a0), "r"(a1), "r"(a2), "r"(a3), "r"(b0), "r"(b1));
}
__device__ __forceinline__ void cp16(uint32_t dst, const void* src) {
    asm volatile("cp.async.cg.shared.global [%0], [%1], 16;" :: "r"(dst), "l"(src));
}
#define CP_COMMIT() asm volatile("cp.async.commit_group;")
#define CP_WAIT(n)  asm volatile("cp.async.wait_group %0;" :: "n"(n))

// ---------------- rmsnorm stage 1 ----------------
__global__ void rmsnorm_kernel(const float* __restrict__ in,
                               const float* __restrict__ w,
                               float* __restrict__ out) {
    int t = blockIdx.x;
    const float* x = in + (size_t)t * H_;
    __shared__ float red[256];
    float ss = 0.f;
    for (int i = threadIdx.x; i < H_; i += 256) { float v = x[i]; ss += v * v; }
    red[threadIdx.x] = ss; __syncthreads();
    for (int s = 128; s > 0; s >>= 1) {
        if (threadIdx.x < s) red[threadIdx.x] += red[threadIdx.x + s];
        __syncthreads();
    }
    float r = rsqrtf(red[0] / (float)H_ + EPS_);
    for (int i = threadIdx.x; i < H_; i += 256)
        out[(size_t)t * H_ + i] = roundtf(x[i] * w[i] * r);
}

// ------ unified tf32 GEMM: BK32 chunks, 3-stage cp.async, 256thr, 2/SM ------
// MODE 0: raw partial, grid (N/128, M/128, SPLIT)
// MODE 2: +bias swiglu round -> act (SPLIT=1), expert grid, tokof A-indirect
// MODE 3: raw partial, expert grid
#define ALD 36
#define BLD 136
#define GSTG 3
#define A_ST (128 * ALD)
#define B_ST (32 * BLD)
#define GEMM_SMEM (GSTG * (A_ST + B_ST) * 4)
template<int MODE, int SPLIT>
__global__ __launch_bounds__(256, 2) void gemm_tf32(
    const float* __restrict__ A, const float* __restrict__ Bw,
    const float* __restrict__ bias,
    float* __restrict__ C, int K, int N, int partStride,
    const int* __restrict__ eoff, const int* __restrict__ ecnt,
    const int* __restrict__ tokof) {
    extern __shared__ uint32_t gsm[];
    uint32_t* As = gsm;                  // [GSTG][128][ALD]
    uint32_t* Bs = gsm + GSTG * A_ST;    // [GSTG][32][BLD]
    int tid = threadIdx.x, lane = tid & 31, wid = tid >> 5;
    int n0 = blockIdx.x * 128;
    int m0, split;
    if (MODE >= 2) {
        int e = blockIdx.z / SPLIT;
        split = blockIdx.z % SPLIT;
        if ((int)blockIdx.y * 128 >= ecnt[e]) return;
        m0 = eoff[e] + blockIdx.y * 128;
        Bw += (size_t)e * K * N;
        if (MODE == 2) bias += (size_t)e * N;
    } else {
        split = blockIdx.z;
        m0 = blockIdx.y * 128;
    }
    int Ksub = K / SPLIT;
    int kbase = split * Ksub;
    C += (size_t)split * partStride;
    int wm = (wid >> 2) * 64, wn = (wid & 3) * 32;   // warps 2m x 4n, 64x32

    uint32_t a_base = (uint32_t)__cvta_generic_to_shared(As);
    uint32_t b_base = (uint32_t)__cvta_generic_to_shared(Bs);
    int arow = tid >> 1;                 // 128 rows, 2 threads/row
    int au0 = (tid & 1) * 4;             // 4 of 8 16B-units
    int brow = tid >> 3;                 // 32 rows, 8 threads/row
    int bu0 = (tid & 7) * 4;             // 4 of 32 16B-units

    const float* aptr;
    if (MODE == 2 && tokof) {
        int a = tokof[m0 + arow];
        aptr = A + (size_t)(a < 0 ? 0 : (a >> 1)) * K;
    } else {
        aptr = A + (size_t)(m0 + arow) * K;
    }

    float acc[16][4];
    #pragma unroll
    for (int i = 0; i < 16; i++)
        #pragma unroll
        for (int j = 0; j < 4; j++) acc[i][j] = 0.f;

    int nch = Ksub / 32;
    auto issue = [&](int c, int s) {
        int k0 = kbase + c * 32;
        #pragma unroll
        for (int u = 0; u < 4; u++) {
            int au = au0 + u;
            cp16(a_base + (((s * 128 + arow) * ALD) + au * 4) * 4,
                 aptr + k0 + au * 4);
        }
        #pragma unroll
        for (int u = 0; u < 4; u++) {
            int bu = bu0 + u;
            cp16(b_base + (((s * 32 + brow) * BLD) + bu * 4) * 4,
                 &Bw[(size_t)(k0 + brow) * N + n0 + bu * 4]);
        }
        CP_COMMIT();
    };

    issue(0, 0);
    if (nch > 1) issue(1, 1);
    for (int c = 0; c < nch; c++) {
        int s = c % 3;
        if (c == nch - 1) { CP_WAIT(0); } else { CP_WAIT(1); }
        __syncthreads();
        if (c + 2 < nch) issue(c + 2, (c + 2) % 3);
        #pragma unroll
        for (int ks = 0; ks < 4; ks++) {
            int kq = ks * 8 + (lane & 3);
            uint32_t b[4][2];
            #pragma unroll
            for (int ni = 0; ni < 4; ni++) {
                int n = wn + ni * 8 + (lane >> 2);
                b[ni][0] = f2tf_bits(Bs[(s * 32 + kq) * BLD + n]);
                b[ni][1] = f2tf_bits(Bs[(s * 32 + kq + 4) * BLD + n]);
            }
            #pragma unroll
            for (int mi = 0; mi < 4; mi++) {
                int m = wm + mi * 16 + (lane >> 2);
                uint32_t a0 = As[(s * 128 + m) * ALD + kq];
                uint32_t a1 = As[(s * 128 + m + 8) * ALD + kq];
                uint32_t a2 = As[(s * 128 + m) * ALD + kq + 4];
                uint32_t a3 = As[(s * 128 + m + 8) * ALD + kq + 4];
                #pragma unroll
                for (int ni = 0; ni < 4; ni++)
                    mma8(acc[mi * 4 + ni], a0, a1, a2, a3, b[ni][0], b[ni][1]);
            }
        }
    }
    #pragma unroll
    for (int mi = 0; mi < 4; mi++) {
        #pragma unroll
        for (int ni = 0; ni < 4; ni++) {
            float* cc = acc[mi * 4 + ni];
            int row = m0 + wm + mi * 16 + (lane >> 2);
            int col = n0 + wn + ni * 8 + 2 * (lane & 3);
            #pragma unroll
            for (int h = 0; h < 2; h++) {
                int r = row + h * 8;
                float v0 = cc[h * 2 + 0];
                float v1 = cc[h * 2 + 1];
                if (MODE == 2) {
                    float g = fminf(v0 + bias[col], LIMIT_);
                    float u = fminf(fmaxf(v1 + bias[col + 1], -LIMIT_), LIMIT_);
                    float glu = g / (1.f + expf(-g * ALPHA_));
                    C[(size_t)r * (N >> 1) + (col >> 1)] = roundtf((u + 1.f) * glu);
                } else {
                    *(float2*)&C[(size_t)r * N + col] = make_float2(v0, v1);
                }
            }
        }
    }
}

// ---------------- tensor-core sliding-window attention (2 qkv partials) ------
#define QLD 68
#define KVLD 72
#define PLD 148
#define ATT_SMEM ((64 * QLD + 2 * 144 * KVLD + 64 * PLD + 64) * 4)
__global__ void attn_mma(const float* __restrict__ qkvp,
                         const float* __restrict__ bqkv,
                         const float* __restrict__ kvc,
                         const int* __restrict__ pidx,
                         const float* __restrict__ sinks,
                         float* __restrict__ attn) {
    extern __shared__ float sm[];
    float* Qs = sm;
    float* Ks = Qs + 64 * QLD;
    float* Vs = Ks + 144 * KVLD;
    float* Ps = Vs + 144 * KVLD;
    float* dinv = Ps + 64 * PLD;
    int qt = blockIdx.x, kv = blockIdx.y, b = blockIdx.z;
    int tid = threadIdx.x, lane = tid & 31, wid = tid >> 5;
    int qpos0 = S_ - Q_ + qt * 16;
    int base = qpos0 - (SW_ - 1);

    #pragma unroll
    for (int l = 0; l < 4; l++) {
        int f = tid + 256 * l;
        int r = f >> 4, d4 = f & 15;
        int ql = r >> 2, g = r & 3;
        size_t o = (size_t)(b * Q_ + qt * 16 + ql) * QKVD + (kv * G_ + g) * HD_ + d4 * 4;
        float4 acc = *(const float4*)&bqkv[(kv * G_ + g) * HD_ + d4 * 4];
        #pragma unroll
        for (int j = 0; j < QKV_SPLIT; j++) {
            float4 a = *(const float4*)&qkvp[(size_t)j * T_ * QKVD + o];
            acc.x += a.x; acc.y += a.y; acc.z += a.z; acc.w += a.w;
        }
        Qs[r * QLD + d4 * 4 + 0] = roundtf(acc.x * SCALE_);
        Qs[r * QLD + d4 * 4 + 1] = roundtf(acc.y * SCALE_);
        Qs[r * QLD + d4 * 4 + 2] = roundtf(acc.z * SCALE_);
        Qs[r * QLD + d4 * 4 + 3] = roundtf(acc.w * SCALE_);
    }
    for (int f = tid; f < 143 * 16; f += 256) {
        int k = f >> 4, d4 = f & 15;
        int kpos = base + k;
        float4 kf, vf;
        if (kpos < S_ - Q_) {
            int page = pidx[b * P_ + (kpos >> 7)];
            size_t o = (((size_t)page * 2) * PS_ + (kpos & 127)) * NKV_ + kv;
            kf = *(const float4*)&kvc[o * HD_ + d4 * 4];
            vf = *(const float4*)&kvc[(o + (size_t)PS_ * NKV_) * HD_ + d4 * 4];
        } else {
            size_t t = (size_t)(b * Q_ + kpos - (S_ - Q_)) * QKVD;
            int ck = NQ_ * HD_ + kv * HD_ + d4 * 4;
            int cv = (NQ_ + NKV_) * HD_ + kv * HD_ + d4 * 4;
            kf = *(const float4*)&bqkv[ck];
            vf = *(const float4*)&bqkv[cv];
            #pragma unroll
            for (int j = 0; j < QKV_SPLIT; j++) {
                float4 a = *(const float4*)&qkvp[(size_t)j * T_ * QKVD + t + ck];
                kf.x += a.x; kf.y += a.y; kf.z += a.z; kf.w += a.w;
                float4 c = *(const float4*)&qkvp[(size_t)j * T_ * QKVD + t + cv];
                vf.x += c.x; vf.y += c.y; vf.z += c.z; vf.w += c.w;
            }
        }
        *(float4*)&Ks[k * KVLD + d4 * 4] = kf;
        *(float4*)&Vs[k * KVLD + d4 * 4] = vf;
    }
    if (tid < 32) {
        int d4 = tid & 15;
        if (tid < 16) *(float4*)&Ks[143 * KVLD + d4 * 4] = make_float4(0, 0, 0, 0);
        else          *(float4*)&Vs[143 * KVLD + d4 * 4] = make_float4(0, 0, 0, 0);
    }
    __syncthreads();

    int mt = wid & 3, nh = wid >> 2;
    int r0 = mt * 16 + (lane >> 2);
    {
        float sacc[9][4];
        #pragma unroll
        for (int i = 0; i < 9; i++)
            #pragma unroll
            for (int j = 0; j < 4; j++) sacc[i][j] = 0.f;
        #pragma unroll
        for (int kk = 0; kk < 8; kk++) {
            int kq = kk * 8 + (lane & 3);
            uint32_t a0 = __float_as_uint(Qs[r0 * QLD + kq]);
            uint32_t a1 = __float_as_uint(Qs[(r0 + 8) * QLD + kq]);
            uint32_t a2 = __float_as_uint(Qs[r0 * QLD + kq + 4]);
            uint32_t a3 = __float_as_uint(Qs[(r0 + 8) * QLD + kq + 4]);
            #pragma unroll
            for (int ni = 0; ni < 9; ni++) {
                int n = nh * 72 + ni * 8 + (lane >> 2);
                uint32_t b0 = f2tf_bits(__float_as_uint(Ks[n * KVLD + kq]));
                uint32_t b1 = f2tf_bits(__float_as_uint(Ks[n * KVLD + kq + 4]));
                mma8(sacc[ni], a0, a1, a2, a3, b0, b1);
            }
        }
        #pragma unroll
        for (int ni = 0; ni < 9; ni++) {
            #pragma unroll
            for (int h = 0; h < 2; h++) {
                int row = r0 + h * 8;
                int ql = row >> 2;
                int cb = nh * 72 + ni * 8 + 2 * (lane & 3);
                float v0 = sacc[ni][h * 2 + 0];
                float v1 = sacc[ni][h * 2 + 1];
                if (cb < ql || cb > ql + 127) v0 = -1e30f;
                if (cb + 1 < ql || cb + 1 > ql + 127) v1 = -1e30f;
                Ps[row * PLD + cb] = v0;
                Ps[row * PLD + cb + 1] = v1;
            }
        }
    }
    __syncthreads();
    {
        int row = tid >> 2, part = tid & 3;
        float mx = -1e30f;
        #pragma unroll 4
        for (int j = 0; j < 36; j++)
            mx = fmaxf(mx, Ps[row * PLD + part * 36 + j]);
        mx = fmaxf(mx, __shfl_xor_sync(0xffffffffu, mx, 1));
        mx = fmaxf(mx, __shfl_xor_sync(0xffffffffu, mx, 2));
        float sum = 0.f;
        #pragma unroll 4
        for (int j = 0; j < 36; j++) {
            float p = expf(Ps[row * PLD + part * 36 + j] - mx);
            Ps[row * PLD + part * 36 + j] = roundtf(p);
            sum += p;
        }
        sum += __shfl_xor_sync(0xffffffffu, sum, 1);
        sum += __shfl_xor_sync(0xffffffffu, sum, 2);
        if (part == 0)
            dinv[row] = 1.f / (sum + expf(sinks[kv * G_ + (row & 3)] - mx));
    }
    __syncthreads();
    {
        float oacc[4][4];
        #pragma unroll
        for (int i = 0; i < 4; i++)
            #pragma unroll
            for (int j = 0; j < 4; j++) oacc[i][j] = 0.f;
        #pragma unroll 2
        for (int kk = 0; kk < 18; kk++) {
            int kq = kk * 8 + (lane & 3);
            uint32_t a0 = __float_as_uint(Ps[r0 * PLD + kq]);
            uint32_t a1 = __float_as_uint(Ps[(r0 + 8) * PLD + kq]);
            uint32_t a2 = __float_as_uint(Ps[r0 * PLD + kq + 4]);
            uint32_t a3 = __float_as_uint(Ps[(r0 + 8) * PLD + kq + 4]);
            #pragma unroll
            for (int ni = 0; ni < 4; ni++) {
                int n = nh * 32 + ni * 8 + (lane >> 2);
                uint32_t b0 = f2tf_bits(__float_as_uint(Vs[kq * KVLD + n]));
                uint32_t b1 = f2tf_bits(__float_as_uint(Vs[(kq + 4) * KVLD + n]));
                mma8(oacc[ni], a0, a1, a2, a3, b0, b1);
            }
        }
        #pragma unroll
        for (int ni = 0; ni < 4; ni++) {
            #pragma unroll
            for (int h = 0; h < 2; h++) {
                int row = r0 + h * 8;
                float di = dinv[row];
                int t = b * Q_ + qt * 16 + (row >> 2);
                int head = kv * G_ + (row & 3);
                int col = nh * 32 + ni * 8 + 2 * (lane & 3);
                float2 o;
                o.x = roundtf(oacc[ni][h * 2 + 0] * di);
                o.y = roundtf(oacc[ni][h * 2 + 1] * di);
                *(float2*)&attn[(size_t)t * (NQ_ * HD_) + head * HD_ + col] = o;
            }
        }
    }
}

// ------- fused: o-proj reduce + residual + bias -> out; rmsnorm2; router ----
__global__ void out_rms_router(const float* __restrict__ p,
                               const float* __restrict__ hidden,
                               const float* __restrict__ bo,
                               const float* __restrict__ ln2,
                               const float* __restrict__ wr,
                               const float* __restrict__ br,
                               float* __restrict__ out,
                               float* __restrict__ x2,
                               int* __restrict__ eidx, float* __restrict__ ewt) {
    int t = blockIdx.x, tid = threadIdx.x;
    float4 r = ((const float4*)(hidden + (size_t)t * H_))[tid];
    float4 bb = ((const float4*)bo)[tid];
    r.x += bb.x; r.y += bb.y; r.z += bb.z; r.w += bb.w;
    #pragma unroll
    for (int s = 0; s < OPJ_SPLIT; s++) {
        float4 a = ((const float4*)(p + (size_t)(s * T_ + t) * H_))[tid];
        r.x += a.x; r.y += a.y; r.z += a.z; r.w += a.w;
    }
    ((float4*)(out + (size_t)t * H_))[tid] = r;

    __shared__ float red[256];
    __shared__ float lac[256][E_];
    red[tid] = r.x * r.x + r.y * r.y + r.z * r.z + r.w * r.w;
    __syncthreads();
    for (int s = 128; s > 0; s >>= 1) {
        if (tid < s) red[tid] += red[tid + s];
        __syncthreads();
    }
    float rinv = rsqrtf(red[0] / (float)H_ + EPS_);
    float4 w4 = ((const float4*)ln2)[tid];
    float v[4] = {r.x * w4.x * rinv, r.y * w4.y * rinv,
                  r.z * w4.z * rinv, r.w * w4.w * rinv};
    float4 xo;
    xo.x = roundtf(v[0]); xo.y = roundtf(v[1]);
    xo.z = roundtf(v[2]); xo.w = roundtf(v[3]);
    ((float4*)(x2 + (size_t)t * H_))[tid] = xo;
    float acc[E_];
    #pragma unroll
    for (int e = 0; e < E_; e++) acc[e] = 0.f;
    #pragma unroll
    for (int j = 0; j < 4; j++) {
        int c = tid * 4 + j;
        #pragma unroll
        for (int e = 0; e < E_; e++) acc[e] += v[j] * wr[c * E_ + e];
    }
    #pragma unroll
    for (int e = 0; e < E_; e++) lac[tid][e] = acc[e];
    __syncthreads();
    for (int s = 128; s > 0; s >>= 1) {
        if (tid < s)
            #pragma unroll
            for (int e = 0; e < E_; e++) lac[tid][e] += lac[tid + s][e];
        __syncthreads();
    }
    if (tid == 0) {
        float l[E_];
        #pragma unroll
        for (int e = 0; e < E_; e++) l[e] = lac[0][e] + br[e];
        int i0 = 0; float v0 = l[0];
        #pragma unroll
        for (int e = 1; e < E_; e++) if (l[e] > v0) { v0 = l[e]; i0 = e; }
        int i1 = -1; float v1 = -1e30f;
        #pragma unroll
        for (int e = 0; e < E_; e++)
            if (e != i0 && l[e] > v1) { v1 = l[e]; i1 = e; }
        float e1 = expf(v1 - v0);
        float inv = 1.f / (1.f + e1);
        eidx[t * 2 + 0] = i0; eidx[t * 2 + 1] = i1;
        ewt[t * 2 + 0] = inv; ewt[t * 2 + 1] = e1 * inv;
    }
}

// ---------------- route sort ----------------
__global__ void route_sort_kernel(const int* __restrict__ eidx,
                                  int* __restrict__ eoff, int* __restrict__ ecnt,
                                  int* __restrict__ tokof, int* __restrict__ slotmap) {
    __shared__ int cnt[E_];
    __shared__ int pos[E_];
    int tid = threadIdx.x;
    if (tid < E_) cnt[tid] = 0;
    for (int i = tid; i < NAPAD; i += 256) tokof[i] = -1;
    __syncthreads();
    for (int a = tid; a < T_ * 2; a += 256) atomicAdd(&cnt[eidx[a]], 1);
    __syncthreads();
    if (tid == 0) {
        int off = 0;
        for (int e = 0; e < E_; e++) {
            eoff[e] = off; ecnt[e] = cnt[e]; pos[e] = off;
            off += ((cnt[e] + 127) / 128) * 128;
        }
    }
    __syncthreads();
    for (int a = tid; a < T_ * 2; a += 256) {
        int e = eidx[a];
        int slot = atomicAdd(&pos[e], 1);
        tokof[slot] = a;
        slotmap[a] = slot;
    }
}

// ---------------- combine ----------------
__global__ void combine_kernel(const float* __restrict__ eop,
                               const int* __restrict__ slotmap,
                               const int* __restrict__ eidx,
                               const float* __restrict__ ewt,
                               const float* __restrict__ bd,
                               float* __restrict__ out) {
    int t = blockIdx.x, i = threadIdx.x;
    float4 o = ((float4*)(out + (size_t)t * H_))[i];
    #pragma unroll
    for (int ei = 0; ei < 2; ei++) {
        int s = slotmap[t * 2 + ei];
        int e = eidx[t * 2 + ei];
        float w = ewt[t * 2 + ei];
        float4 a = ((const float4*)(bd + (size_t)e * H_))[i];
        #pragma unroll
        for (int sp = 0; sp < DN_SPLIT; sp++) {
            float4 b = ((const float4*)(eop + (size_t)(sp * NAPAD + s) * H_))[i];
            a.x += b.x; a.y += b.y; a.z += b.z; a.w += b.w;
        }
        o.x += w * a.x; o.y += w * a.y; o.z += w * a.z; o.w += w * a.w;
    }
    ((float4*)(out + (size_t)t * H_))[i] = o;
}

// ---------------- launch ----------------
extern "C" void kernel_launch(void* const* d_in, const int* in_sizes, int n_in,
                              void* d_out, int out_size) {
    const float* hidden = (const float*)d_in[0];
    const float* kvc    = (const float*)d_in[1];
    const int*   pidx   = (const int*)d_in[3];
    const float* sinks  = (const float*)d_in[4];
    const float* w_qkv  = (const float*)d_in[5];
    const float* b_qkv  = (const float*)d_in[6];
    const float* w_o    = (const float*)d_in[7];
    const float* b_o    = (const float*)d_in[8];
    const float* ln1    = (const float*)d_in[9];
    const float* ln2    = (const float*)d_in[10];
    const float* w_r    = (const float*)d_in[11];
    const float* b_r    = (const float*)d_in[12];
    const float* w_gu   = (const float*)d_in[13];
    const float* b_gu   = (const float*)d_in[14];
    const float* w_d    = (const float*)d_in[15];
    const float* b_d    = (const float*)d_in[16];
    float* out = (float*)d_out;

    float *px, *pqkvp, *pattn, *poutp, *px2, *pewt, *pact, *peop;
    int *peidx, *peoff, *pecnt, *ptokof, *pslot;
    cudaGetSymbolAddress((void**)&px,     g_x);
    cudaGetSymbolAddress((void**)&pqkvp,  g_qkvp);
    cudaGetSymbolAddress((void**)&pattn,  g_attn);
    cudaGetSymbolAddress((void**)&poutp,  g_outp);
    cudaGetSymbolAddress((void**)&px2,    g_x2);
    cudaGetSymbolAddress((void**)&peidx,  g_eidx);
    cudaGetSymbolAddress((void**)&pewt,   g_ewt);
    cudaGetSymbolAddress((void**)&peoff,  g_eoff);
    cudaGetSymbolAddress((void**)&pecnt,  g_ecnt);
    cudaGetSymbolAddress((void**)&ptokof, g_tokof);
    cudaGetSymbolAddress((void**)&pslot,  g_slotmap);
    cudaGetSymbolAddress((void**)&pact,   g_act);
    cudaGetSymbolAddress((void**)&peop,   g_eop);

    cudaFuncSetAttribute(attn_mma,
                         cudaFuncAttributeMaxDynamicSharedMemorySize, ATT_SMEM);
    cudaFuncSetAttribute(gemm_tf32<0, QKV_SPLIT>,
                         cudaFuncAttributeMaxDynamicSharedMemorySize, GEMM_SMEM);
    cudaFuncSetAttribute(gemm_tf32<0, OPJ_SPLIT>,
                         cudaFuncAttributeMaxDynamicSharedMemorySize, GEMM_SMEM);
    cudaFuncSetAttribute(gemm_tf32<2, 1>,
                         cudaFuncAttributeMaxDynamicSharedMemorySize, GEMM_SMEM);
    cudaFuncSetAttribute(gemm_tf32<3, DN_SPLIT>,
                         cudaFuncAttributeMaxDynamicSharedMemorySize, GEMM_SMEM);

    rmsnorm_kernel<<<T_, 256>>>(hidden, ln1, px);
    gemm_tf32<0, QKV_SPLIT><<<dim3(QKVD / 128, T_ / 128, QKV_SPLIT),
                              256, GEMM_SMEM>>>(
        px, w_qkv, nullptr, pqkvp, H_, QKVD, T_ * QKVD, nullptr, nullptr, nullptr);
    attn_mma<<<dim3(Q_ / 16, NKV_, B_), 256, ATT_SMEM>>>(
        pqkvp, b_qkv, kvc, pidx, sinks, pattn);
    gemm_tf32<0, OPJ_SPLIT><<<dim3(H_ / 128, T_ / 128, OPJ_SPLIT),
                              256, GEMM_SMEM>>>(
        pattn, w_o, nullptr, poutp, H_, H_, T_ * H_, nullptr, nullptr, nullptr);
    out_rms_router<<<T_, 256>>>(poutp, hidden, b_o, ln2, w_r, b_r,
                                out, px2, peidx, pewt);
    route_sort_kernel<<<1, 256>>>(peidx, peoff, pecnt, ptokof, pslot);
    gemm_tf32<2, 1><<<dim3(2 * FFN_ / 128, NAPAD / 128, E_), 256, GEMM_SMEM>>>(
        px2, w_gu, b_gu, pact, H_, 2 * FFN_, 0, peoff, pecnt, ptokof);
    gemm_tf32<3, DN_SPLIT><<<dim3(H_ / 128, NAPAD / 128, E_ * DN_SPLIT),
                             256, GEMM_SMEM>>>(
        pact, w_d, nullptr, peop, FFN_, H_, NAPAD * H_, peoff, pecnt, nullptr);
    combine_kernel<<<T_, 256>>>(peop, pslot, peidx, pewt, b_d, out);
}

// round 13
// speedup vs baseline: 1.1465x; 1.1465x over previous
#include <cuda_runtime.h>
#include <cstdint>
#include <math.h>

#define T_    512
#define H_    1024
#define HD_   64
#define NQ_   16
#define NKV_  4
#define G_    4
#define E_    8
#define FFN_  1024
#define B_    4
#define Q_    128
#define P_    8
#define PS_   128
#define S_    1024
#define SW_   128
#define QKVD  1536
#define SCALE_ 0.125f
#define ALPHA_ 1.702f
#define LIMIT_ 7.0f
#define EPS_   1e-5f
#define NAPAD 2048

#define QKV_SPLIT 2
#define OPJ_SPLIT 4
#define DN_SPLIT  2

// ---------------- scratch ----------------
__device__ float g_x[T_ * H_];
__device__ float g_qkvp[QKV_SPLIT * T_ * QKVD];
__device__ float g_attn[T_ * NQ_ * HD_];
__device__ float g_outp[OPJ_SPLIT * T_ * H_];
__device__ float g_x2[T_ * H_];
__device__ int   g_eidx[T_ * 2];
__device__ float g_ewt[T_ * 2];
__device__ int   g_eoff[E_];
__device__ int   g_ecnt[E_];
__device__ int   g_tokof[NAPAD];
__device__ int   g_slotmap[T_ * 2];
__device__ float g_act[NAPAD * FFN_];
__device__ float g_eop[DN_SPLIT * NAPAD * H_];

// ---------------- helpers ----------------
__device__ __forceinline__ uint32_t f2tf_bits(uint32_t bits) {
    uint32_t r;
    asm("cvt.rna.tf32.f32 %0, %1;" : "=r"(r) : "f"(__uint_as_float(bits)));
    return r;
}
__device__ __forceinline__ float roundtf(float f) {
    uint32_t r;
    asm("cvt.rna.tf32.f32 %0, %1;" : "=r"(r) : "f"(f));
    return __uint_as_float(r);
}
__device__ __forceinline__ void mma8(float* c, uint32_t a0, uint32_t a1,
                                     uint32_t a2, uint32_t a3,
                                     uint32_t b0, uint32_t b1) {
    asm volatile("mma.sync.aligned.m16n8k8.row.col.f32.tf32.tf32.f32 "
        "{%0,%1,%2,%3}, {%4,%5,%6,%7}, {%8,%9}, {%0,%1,%2,%3};"
        : "+f"(c[0]), "+f"(c[1]), "+f"(c[2]), "+f"(c[3])
        : "r"(a0), "r"(a1), "r"(a2), "r"(a3), "r"(b0), "r"(b1));
}
__device__ __forceinline__ void cp16(uint32_t dst, const void* src) {
    asm volatile("cp.async.cg.shared.global [%0], [%1], 16;" :: "r"(dst), "l"(src));
}
#define CP_COMMIT() asm volatile("cp.async.commit_group;")
#define CP_WAIT(n)  asm volatile("cp.async.wait_group %0;" :: "n"(n))

// ---------------- rmsnorm stage 1 ----------------
__global__ void rmsnorm_kernel(const float* __restrict__ in,
                               const float* __restrict__ w,
                               float* __restrict__ out) {
    int t = blockIdx.x;
    const float* x = in + (size_t)t * H_;
    __shared__ float red[256];
    float ss = 0.f;
    for (int i = threadIdx.x; i < H_; i += 256) { float v = x[i]; ss += v * v; }
    red[threadIdx.x] = ss; __syncthreads();
    for (int s = 128; s > 0; s >>= 1) {
        if (threadIdx.x < s) red[threadIdx.x] += red[threadIdx.x + s];
        __syncthreads();
    }
    float r = rsqrtf(red[0] / (float)H_ + EPS_);
    for (int i = threadIdx.x; i < H_; i += 256)
        out[(size_t)t * H_ + i] = roundtf(x[i] * w[i] * r);
}

// ------ unified tf32 GEMM: BK16, 4-stage cp.async, 256 thr, 2 blocks/SM -----
// MODE 0: raw partial, grid (N/128, M/128, SPLIT)
// MODE 2: +bias swiglu round -> act (SPLIT=1), expert grid, tokof A-indirect
// MODE 3: raw partial, expert grid
#define ALD 20
#define BLD 136
#define GSTG 4
#define GEMM_SMEM ((GSTG * 128 * ALD + GSTG * 16 * BLD) * 4)
template<int MODE, int SPLIT>
__global__ __launch_bounds__(256, 2) void gemm_tf32(
    const float* __restrict__ A, const float* __restrict__ Bw,
    const float* __restrict__ bias,
    float* __restrict__ C, int K, int N, int partStride,
    const int* __restrict__ eoff, const int* __restrict__ ecnt,
    const int* __restrict__ tokof) {
    extern __shared__ uint32_t gsm[];
    uint32_t* As = gsm;                         // [GSTG][128][ALD]
    uint32_t* Bs = gsm + GSTG * 128 * ALD;      // [GSTG][16][BLD]
    int tid = threadIdx.x, lane = tid & 31, wid = tid >> 5;
    int n0 = blockIdx.x * 128;
    int m0, split;
    if (MODE >= 2) {
        int e = blockIdx.z / SPLIT;
        split = blockIdx.z % SPLIT;
        if ((int)blockIdx.y * 128 >= ecnt[e]) return;
        m0 = eoff[e] + blockIdx.y * 128;
        Bw += (size_t)e * K * N;
        if (MODE == 2) bias += (size_t)e * N;
    } else {
        split = blockIdx.z;
        m0 = blockIdx.y * 128;
    }
    int Ksub = K / SPLIT;
    int kbase = split * Ksub;
    C += (size_t)split * partStride;
    int wm = (wid >> 2) * 64, wn = (wid & 3) * 32;

    uint32_t a_base = (uint32_t)__cvta_generic_to_shared(As);
    uint32_t b_base = (uint32_t)__cvta_generic_to_shared(Bs);
    int arow0 = tid >> 1, ac0 = (tid & 1) * 2;
    int brow0 = tid >> 4, bc0 = tid & 15;

    const float* aptr;
    if (MODE == 2 && tokof) {
        int a = tokof[m0 + arow0];
        aptr = A + (size_t)(a < 0 ? 0 : (a >> 1)) * K;
    } else {
        aptr = A + (size_t)(m0 + arow0) * K;
    }

    float acc[16][4];
    #pragma unroll
    for (int i = 0; i < 16; i++)
        #pragma unroll
        for (int j = 0; j < 4; j++) acc[i][j] = 0.f;

    int nchunks = Ksub / 16;
    auto issue = [&](int c, int s) {
        int k0 = kbase + c * 16;
        #pragma unroll
        for (int l = 0; l < 2; l++) {
            int c4 = ac0 + l;
            cp16(a_base + (((s * 128 + arow0) * ALD) + c4 * 4) * 4,
                 aptr + k0 + c4 * 4);
        }
        #pragma unroll
        for (int l = 0; l < 2; l++) {
            int cc = bc0 * 2 + l;
            cp16(b_base + (((s * 16 + brow0) * BLD) + cc * 4) * 4,
                 &Bw[(size_t)(k0 + brow0) * N + n0 + cc * 4]);
        }
        CP_COMMIT();
    };

    issue(0, 0); issue(1, 1); issue(2, 2);
    for (int c = 0; c < nchunks; c++) {
        CP_WAIT(2);
        __syncthreads();
        if (c + 3 < nchunks) issue(c + 3, (c + 3) & 3); else CP_COMMIT();
        int s = c & 3;
        #pragma unroll
        for (int ks = 0; ks < 2; ks++) {
            int kq = ks * 8 + (lane & 3);
            uint32_t b[4][2];
            #pragma unroll
            for (int ni = 0; ni < 4; ni++) {
                int n = wn + ni * 8 + (lane >> 2);
                b[ni][0] = f2tf_bits(Bs[(s * 16 + kq) * BLD + n]);
                b[ni][1] = f2tf_bits(Bs[(s * 16 + kq + 4) * BLD + n]);
            }
            #pragma unroll
            for (int mi = 0; mi < 4; mi++) {
                int m = wm + mi * 16 + (lane >> 2);
                uint32_t a0 = As[(s * 128 + m) * ALD + kq];
                uint32_t a1 = As[(s * 128 + m + 8) * ALD + kq];
                uint32_t a2 = As[(s * 128 + m) * ALD + kq + 4];
                uint32_t a3 = As[(s * 128 + m + 8) * ALD + kq + 4];
                #pragma unroll
                for (int ni = 0; ni < 4; ni++)
                    mma8(acc[mi * 4 + ni], a0, a1, a2, a3, b[ni][0], b[ni][1]);
            }
        }
    }
    #pragma unroll
    for (int mi = 0; mi < 4; mi++) {
        #pragma unroll
        for (int ni = 0; ni < 4; ni++) {
            float* cc = acc[mi * 4 + ni];
            int row = m0 + wm + mi * 16 + (lane >> 2);
            int col = n0 + wn + ni * 8 + 2 * (lane & 3);
            #pragma unroll
            for (int h = 0; h < 2; h++) {
                int r = row + h * 8;
                float v0 = cc[h * 2 + 0];
                float v1 = cc[h * 2 + 1];
                if (MODE == 2) {
                    float g = fminf(v0 + bias[col], LIMIT_);
                    float u = fminf(fmaxf(v1 + bias[col + 1], -LIMIT_), LIMIT_);
                    float glu = g / (1.f + expf(-g * ALPHA_));
                    C[(size_t)r * (N >> 1) + (col >> 1)] = roundtf((u + 1.f) * glu);
                } else {
                    *(float2*)&C[(size_t)r * N + col] = make_float2(v0, v1);
                }
            }
        }
    }
}

// ---------------- tensor-core sliding-window attention (2 qkv partials) ------
#define QLD 68
#define KVLD 72
#define PLD 148
#define ATT_SMEM ((64 * QLD + 2 * 144 * KVLD + 64 * PLD + 64) * 4)
__global__ void attn_mma(const float* __restrict__ qkvp,
                         const float* __restrict__ bqkv,
                         const float* __restrict__ kvc,
                         const int* __restrict__ pidx,
                         const float* __restrict__ sinks,
                         float* __restrict__ attn) {
    extern __shared__ float sm[];
    float* Qs = sm;
    float* Ks = Qs + 64 * QLD;
    float* Vs = Ks + 144 * KVLD;
    float* Ps = Vs + 144 * KVLD;
    float* dinv = Ps + 64 * PLD;
    int qt = blockIdx.x, kv = blockIdx.y, b = blockIdx.z;
    int tid = threadIdx.x, lane = tid & 31, wid = tid >> 5;
    int qpos0 = S_ - Q_ + qt * 16;
    int base = qpos0 - (SW_ - 1);

    #pragma unroll
    for (int l = 0; l < 4; l++) {
        int f = tid + 256 * l;
        int r = f >> 4, d4 = f & 15;
        int ql = r >> 2, g = r & 3;
        size_t o = (size_t)(b * Q_ + qt * 16 + ql) * QKVD + (kv * G_ + g) * HD_ + d4 * 4;
        float4 acc = *(const float4*)&bqkv[(kv * G_ + g) * HD_ + d4 * 4];
        #pragma unroll
        for (int j = 0; j < QKV_SPLIT; j++) {
            float4 a = *(const float4*)&qkvp[(size_t)j * T_ * QKVD + o];
            acc.x += a.x; acc.y += a.y; acc.z += a.z; acc.w += a.w;
        }
        Qs[r * QLD + d4 * 4 + 0] = roundtf(acc.x * SCALE_);
        Qs[r * QLD + d4 * 4 + 1] = roundtf(acc.y * SCALE_);
        Qs[r * QLD + d4 * 4 + 2] = roundtf(acc.z * SCALE_);
        Qs[r * QLD + d4 * 4 + 3] = roundtf(acc.w * SCALE_);
    }
    for (int f = tid; f < 143 * 16; f += 256) {
        int k = f >> 4, d4 = f & 15;
        int kpos = base + k;
        float4 kf, vf;
        if (kpos < S_ - Q_) {
            int page = pidx[b * P_ + (kpos >> 7)];
            size_t o = (((size_t)page * 2) * PS_ + (kpos & 127)) * NKV_ + kv;
            kf = *(const float4*)&kvc[o * HD_ + d4 * 4];
            vf = *(const float4*)&kvc[(o + (size_t)PS_ * NKV_) * HD_ + d4 * 4];
        } else {
            size_t t = (size_t)(b * Q_ + kpos - (S_ - Q_)) * QKVD;
            int ck = NQ_ * HD_ + kv * HD_ + d4 * 4;
            int cv = (NQ_ + NKV_) * HD_ + kv * HD_ + d4 * 4;
            kf = *(const float4*)&bqkv[ck];
            vf = *(const float4*)&bqkv[cv];
            #pragma unroll
            for (int j = 0; j < QKV_SPLIT; j++) {
                float4 a = *(const float4*)&qkvp[(size_t)j * T_ * QKVD + t + ck];
                kf.x += a.x; kf.y += a.y; kf.z += a.z; kf.w += a.w;
                float4 c = *(const float4*)&qkvp[(size_t)j * T_ * QKVD + t + cv];
                vf.x += c.x; vf.y += c.y; vf.z += c.z; vf.w += c.w;
            }
        }
        *(float4*)&Ks[k * KVLD + d4 * 4] = kf;
        *(float4*)&Vs[k * KVLD + d4 * 4] = vf;
    }
    if (tid < 32) {
        int d4 = tid & 15;
        if (tid < 16) *(float4*)&Ks[143 * KVLD + d4 * 4] = make_float4(0, 0, 0, 0);
        else          *(float4*)&Vs[143 * KVLD + d4 * 4] = make_float4(0, 0, 0, 0);
    }
    __syncthreads();

    int mt = wid & 3, nh = wid >> 2;
    int r0 = mt * 16 + (lane >> 2);
    {
        float sacc[9][4];
        #pragma unroll
        for (int i = 0; i < 9; i++)
            #pragma unroll
            for (int j = 0; j < 4; j++) sacc[i][j] = 0.f;
        #pragma unroll
        for (int kk = 0; kk < 8; kk++) {
            int kq = kk * 8 + (lane & 3);
            uint32_t a0 = __float_as_uint(Qs[r0 * QLD + kq]);
            uint32_t a1 = __float_as_uint(Qs[(r0 + 8) * QLD + kq]);
            uint32_t a2 = __float_as_uint(Qs[r0 * QLD + kq + 4]);
            uint32_t a3 = __float_as_uint(Qs[(r0 + 8) * QLD + kq + 4]);
            #pragma unroll
            for (int ni = 0; ni < 9; ni++) {
                int n = nh * 72 + ni * 8 + (lane >> 2);
                uint32_t b0 = f2tf_bits(__float_as_uint(Ks[n * KVLD + kq]));
                uint32_t b1 = f2tf_bits(__float_as_uint(Ks[n * KVLD + kq + 4]));
                mma8(sacc[ni], a0, a1, a2, a3, b0, b1);
            }
        }
        #pragma unroll
        for (int ni = 0; ni < 9; ni++) {
            #pragma unroll
            for (int h = 0; h < 2; h++) {
                int row = r0 + h * 8;
                int ql = row >> 2;
                int cb = nh * 72 + ni * 8 + 2 * (lane & 3);
                float v0 = sacc[ni][h * 2 + 0];
                float v1 = sacc[ni][h * 2 + 1];
                if (cb < ql || cb > ql + 127) v0 = -1e30f;
                if (cb + 1 < ql || cb + 1 > ql + 127) v1 = -1e30f;
                Ps[row * PLD + cb] = v0;
                Ps[row * PLD + cb + 1] = v1;
            }
        }
    }
    __syncthreads();
    {
        int row = tid >> 2, part = tid & 3;
        float mx = -1e30f;
        #pragma unroll 4
        for (int j = 0; j < 36; j++)
            mx = fmaxf(mx, Ps[row * PLD + part * 36 + j]);
        mx = fmaxf(mx, __shfl_xor_sync(0xffffffffu, mx, 1));
        mx = fmaxf(mx, __shfl_xor_sync(0xffffffffu, mx, 2));
        float sum = 0.f;
        #pragma unroll 4
        for (int j = 0; j < 36; j++) {
            float p = expf(Ps[row * PLD + part * 36 + j] - mx);
            Ps[row * PLD + part * 36 + j] = roundtf(p);
            sum += p;
        }
        sum += __shfl_xor_sync(0xffffffffu, sum, 1);
        sum += __shfl_xor_sync(0xffffffffu, sum, 2);
        if (part == 0)
            dinv[row] = 1.f / (sum + expf(sinks[kv * G_ + (row & 3)] - mx));
    }
    __syncthreads();
    {
        float oacc[4][4];
        #pragma unroll
        for (int i = 0; i < 4; i++)
            #pragma unroll
            for (int j = 0; j < 4; j++) oacc[i][j] = 0.f;
        #pragma unroll 2
        for (int kk = 0; kk < 18; kk++) {
            int kq = kk * 8 + (lane & 3);
            uint32_t a0 = __float_as_uint(Ps[r0 * PLD + kq]);
            uint32_t a1 = __float_as_uint(Ps[(r0 + 8) * PLD + kq]);
            uint32_t a2 = __float_as_uint(Ps[r0 * PLD + kq + 4]);
            uint32_t a3 = __float_as_uint(Ps[(r0 + 8) * PLD + kq + 4]);
            #pragma unroll
            for (int ni = 0; ni < 4; ni++) {
                int n = nh * 32 + ni * 8 + (lane >> 2);
                uint32_t b0 = f2tf_bits(__float_as_uint(Vs[kq * KVLD + n]));
                uint32_t b1 = f2tf_bits(__float_as_uint(Vs[(kq + 4) * KVLD + n]));
                mma8(oacc[ni], a0, a1, a2, a3, b0, b1);
            }
        }
        #pragma unroll
        for (int ni = 0; ni < 4; ni++) {
            #pragma unroll
            for (int h = 0; h < 2; h++) {
                int row = r0 + h * 8;
                float di = dinv[row];
                int t = b * Q_ + qt * 16 + (row >> 2);
                int head = kv * G_ + (row & 3);
                int col = nh * 32 + ni * 8 + 2 * (lane & 3);
                float2 o;
                o.x = roundtf(oacc[ni][h * 2 + 0] * di);
                o.y = roundtf(oacc[ni][h * 2 + 1] * di);
                *(float2*)&attn[(size_t)t * (NQ_ * HD_) + head * HD_ + col] = o;
            }
        }
    }
}

// ------- fused: o-proj reduce + residual + bias -> out; rmsnorm2; router ----
__global__ void out_rms_router(const float* __restrict__ p,
                               const float* __restrict__ hidden,
                               const float* __restrict__ bo,
                               const float* __restrict__ ln2,
                               const float* __restrict__ wr,
                               const float* __restrict__ br,
                               float* __restrict__ out,
                               float* __restrict__ x2,
                               int* __restrict__ eidx, float* __restrict__ ewt) {
    int t = blockIdx.x, tid = threadIdx.x;
    float4 r = ((const float4*)(hidden + (size_t)t * H_))[tid];
    float4 bb = ((const float4*)bo)[tid];
    r.x += bb.x; r.y += bb.y; r.z += bb.z; r.w += bb.w;
    #pragma unroll
    for (int s = 0; s < OPJ_SPLIT; s++) {
        float4 a = ((const float4*)(p + (size_t)(s * T_ + t) * H_))[tid];
        r.x += a.x; r.y += a.y; r.z += a.z; r.w += a.w;
    }
    ((float4*)(out + (size_t)t * H_))[tid] = r;

    __shared__ float red[256];
    __shared__ float lac[256][E_];
    red[tid] = r.x * r.x + r.y * r.y + r.z * r.z + r.w * r.w;
    __syncthreads();
    for (int s = 128; s > 0; s >>= 1) {
        if (tid < s) red[tid] += red[tid + s];
        __syncthreads();
    }
    float rinv = rsqrtf(red[0] / (float)H_ + EPS_);
    float4 w4 = ((const float4*)ln2)[tid];
    float v[4] = {r.x * w4.x * rinv, r.y * w4.y * rinv,
                  r.z * w4.z * rinv, r.w * w4.w * rinv};
    float4 xo;
    xo.x = roundtf(v[0]); xo.y = roundtf(v[1]);
    xo.z = roundtf(v[2]); xo.w = roundtf(v[3]);
    ((float4*)(x2 + (size_t)t * H_))[tid] = xo;
    float acc[E_];
    #pragma unroll
    for (int e = 0; e < E_; e++) acc[e] = 0.f;
    #pragma unroll
    for (int j = 0; j < 4; j++) {
        int c = tid * 4 + j;
        #pragma unroll
        for (int e = 0; e < E_; e++) acc[e] += v[j] * wr[c * E_ + e];
    }
    #pragma unroll
    for (int e = 0; e < E_; e++) lac[tid][e] = acc[e];
    __syncthreads();
    for (int s = 128; s > 0; s >>= 1) {
        if (tid < s)
            #pragma unroll
            for (int e = 0; e < E_; e++) lac[tid][e] += lac[tid + s][e];
        __syncthreads();
    }
    if (tid == 0) {
        float l[E_];
        #pragma unroll
        for (int e = 0; e < E_; e++) l[e] = lac[0][e] + br[e];
        int i0 = 0; float v0 = l[0];
        #pragma unroll
        for (int e = 1; e < E_; e++) if (l[e] > v0) { v0 = l[e]; i0 = e; }
        int i1 = -1; float v1 = -1e30f;
        #pragma unroll
        for (int e = 0; e < E_; e++)
            if (e != i0 && l[e] > v1) { v1 = l[e]; i1 = e; }
        float e1 = expf(v1 - v0);
        float inv = 1.f / (1.f + e1);
        eidx[t * 2 + 0] = i0; eidx[t * 2 + 1] = i1;
        ewt[t * 2 + 0] = inv; ewt[t * 2 + 1] = e1 * inv;
    }
}

// ---------------- route sort ----------------
__global__ void route_sort_kernel(const int* __restrict__ eidx,
                                  int* __restrict__ eoff, int* __restrict__ ecnt,
                                  int* __restrict__ tokof, int* __restrict__ slotmap) {
    __shared__ int cnt[E_];
    __shared__ int pos[E_];
    int tid = threadIdx.x;
    if (tid < E_) cnt[tid] = 0;
    for (int i = tid; i < NAPAD; i += 256) tokof[i] = -1;
    __syncthreads();
    for (int a = tid; a < T_ * 2; a += 256) atomicAdd(&cnt[eidx[a]], 1);
    __syncthreads();
    if (tid == 0) {
        int off = 0;
        for (int e = 0; e < E_; e++) {
            eoff[e] = off; ecnt[e] = cnt[e]; pos[e] = off;
            off += ((cnt[e] + 127) / 128) * 128;
        }
    }
    __syncthreads();
    for (int a = tid; a < T_ * 2; a += 256) {
        int e = eidx[a];
        int slot = atomicAdd(&pos[e], 1);
        tokof[slot] = a;
        slotmap[a] = slot;
    }
}

// ---------------- combine ----------------
__global__ void combine_kernel(const float* __restrict__ eop,
                               const int* __restrict__ slotmap,
                               const int* __restrict__ eidx,
                               const float* __restrict__ ewt,
                               const float* __restrict__ bd,
                               float* __restrict__ out) {
    int t = blockIdx.x, i = threadIdx.x;
    float4 o = ((float4*)(out + (size_t)t * H_))[i];
    #pragma unroll
    for (int ei = 0; ei < 2; ei++) {
        int s = slotmap[t * 2 + ei];
        int e = eidx[t * 2 + ei];
        float w = ewt[t * 2 + ei];
        float4 a = ((const float4*)(bd + (size_t)e * H_))[i];
        #pragma unroll
        for (int sp = 0; sp < DN_SPLIT; sp++) {
            float4 b = ((const float4*)(eop + (size_t)(sp * NAPAD + s) * H_))[i];
            a.x += b.x; a.y += b.y; a.z += b.z; a.w += b.w;
        }
        o.x += w * a.x; o.y += w * a.y; o.z += w * a.z; o.w += w * a.w;
    }
    ((float4*)(out + (size_t)t * H_))[i] = o;
}

// ---------------- launch ----------------
extern "C" void kernel_launch(void* const* d_in, const int* in_sizes, int n_in,
                              void* d_out, int out_size) {
    const float* hidden = (const float*)d_in[0];
    const float* kvc    = (const float*)d_in[1];
    const int*   pidx   = (const int*)d_in[3];
    const float* sinks  = (const float*)d_in[4];
    const float* w_qkv  = (const float*)d_in[5];
    const float* b_qkv  = (const float*)d_in[6];
    const float* w_o    = (const float*)d_in[7];
    const float* b_o    = (const float*)d_in[8];
    const float* ln1    = (const float*)d_in[9];
    const float* ln2    = (const float*)d_in[10];
    const float* w_r    = (const float*)d_in[11];
    const float* b_r    = (const float*)d_in[12];
    const float* w_gu   = (const float*)d_in[13];
    const float* b_gu   = (const float*)d_in[14];
    const float* w_d    = (const float*)d_in[15];
    const float* b_d    = (const float*)d_in[16];
    float* out = (float*)d_out;

    float *px, *pqkvp, *pattn, *poutp, *px2, *pewt, *pact, *peop;
    int *peidx, *peoff, *pecnt, *ptokof, *pslot;
    cudaGetSymbolAddress((void**)&px,     g_x);
    cudaGetSymbolAddress((void**)&pqkvp,  g_qkvp);
    cudaGetSymbolAddress((void**)&pattn,  g_attn);
    cudaGetSymbolAddress((void**)&poutp,  g_outp);
    cudaGetSymbolAddress((void**)&px2,    g_x2);
    cudaGetSymbolAddress((void**)&peidx,  g_eidx);
    cudaGetSymbolAddress((void**)&pewt,   g_ewt);
    cudaGetSymbolAddress((void**)&peoff,  g_eoff);
    cudaGetSymbolAddress((void**)&pecnt,  g_ecnt);
    cudaGetSymbolAddress((void**)&ptokof, g_tokof);
    cudaGetSymbolAddress((void**)&pslot,  g_slotmap);
    cudaGetSymbolAddress((void**)&pact,   g_act);
    cudaGetSymbolAddress((void**)&peop,   g_eop);

    cudaFuncSetAttribute(attn_mma,
                         cudaFuncAttributeMaxDynamicSharedMemorySize, ATT_SMEM);
    cudaFuncSetAttribute(gemm_tf32<0, QKV_SPLIT>,
                         cudaFuncAttributeMaxDynamicSharedMemorySize, GEMM_SMEM);
    cudaFuncSetAttribute(gemm_tf32<0, OPJ_SPLIT>,
                         cudaFuncAttributeMaxDynamicSharedMemorySize, GEMM_SMEM);
    cudaFuncSetAttribute(gemm_tf32<2, 1>,
                         cudaFuncAttributeMaxDynamicSharedMemorySize, GEMM_SMEM);
    cudaFuncSetAttribute(gemm_tf32<3, DN_SPLIT>,
                         cudaFuncAttributeMaxDynamicSharedMemorySize, GEMM_SMEM);

    rmsnorm_kernel<<<T_, 256>>>(hidden, ln1, px);
    gemm_tf32<0, QKV_SPLIT><<<dim3(QKVD / 128, T_ / 128, QKV_SPLIT),
                              256, GEMM_SMEM>>>(
        px, w_qkv, nullptr, pqkvp, H_, QKVD, T_ * QKVD, nullptr, nullptr, nullptr);
    attn_mma<<<dim3(Q_ / 16, NKV_, B_), 256, ATT_SMEM>>>(
        pqkvp, b_qkv, kvc, pidx, sinks, pattn);
    gemm_tf32<0, OPJ_SPLIT><<<dim3(H_ / 128, T_ / 128, OPJ_SPLIT),
                              256, GEMM_SMEM>>>(
        pattn, w_o, nullptr, poutp, H_, H_, T_ * H_, nullptr, nullptr, nullptr);
    out_rms_router<<<T_, 256>>>(poutp, hidden, b_o, ln2, w_r, b_r,
                                out, px2, peidx, pewt);
    route_sort_kernel<<<1, 256>>>(peidx, peoff, pecnt, ptokof, pslot);
    gemm_tf32<2, 1><<<dim3(2 * FFN_ / 128, 8, E_), 256, GEMM_SMEM>>>(
        px2, w_gu, b_gu, pact, H_, 2 * FFN_, 0, peoff, pecnt, ptokof);
    gemm_tf32<3, DN_SPLIT><<<dim3(H_ / 128, 8, E_ * DN_SPLIT),
                             256, GEMM_SMEM>>>(
        pact, w_d, nullptr, peop, FFN_, H_, NAPAD * H_, peoff, pecnt, nullptr);
    combine_kernel<<<T_, 256>>>(peop, pslot, peidx, pewt, b_d, out);
}

// round 14
// speedup vs baseline: 1.4365x; 1.2530x over previous
#include <cuda_runtime.h>
#include <cstdint>
#include <math.h>

#define T_    512
#define H_    1024
#define HD_   64
#define NQ_   16
#define NKV_  4
#define G_    4
#define E_    8
#define FFN_  1024
#define B_    4
#define Q_    128
#define P_    8
#define PS_   128
#define S_    1024
#define SW_   128
#define QKVD  1536
#define SCALE_ 0.125f
#define ALPHA_ 1.702f
#define LIMIT_ 7.0f
#define EPS_   1e-5f
#define NAPAD 2048

#define QKV_SPLIT 2
#define OPJ_SPLIT 4
#define DN_SPLIT  2

// ---------------- scratch ----------------
__device__ float g_x[T_ * H_];
__device__ float g_qkvp[QKV_SPLIT * T_ * QKVD];
__device__ float g_attn[T_ * NQ_ * HD_];
__device__ float g_outp[OPJ_SPLIT * T_ * H_];
__device__ float g_x2[T_ * H_];
__device__ int   g_eidx[T_ * 2];
__device__ float g_ewt[T_ * 2];
__device__ int   g_eoff[E_];
__device__ int   g_ecnt[E_];
__device__ int   g_tokof[NAPAD];
__device__ int   g_slotmap[T_ * 2];
__device__ float g_xg[NAPAD * H_];
__device__ float g_act[NAPAD * FFN_];
__device__ float g_eop[DN_SPLIT * NAPAD * H_];

// ---------------- helpers ----------------
__device__ __forceinline__ uint32_t f2tf_bits(uint32_t bits) {
    uint32_t r;
    asm("cvt.rna.tf32.f32 %0, %1;" : "=r"(r) : "f"(__uint_as_float(bits)));
    return r;
}
__device__ __forceinline__ float roundtf(float f) {
    uint32_t r;
    asm("cvt.rna.tf32.f32 %0, %1;" : "=r"(r) : "f"(f));
    return __uint_as_float(r);
}
__device__ __forceinline__ void mma8(float* c, uint32_t a0, uint32_t a1,
                                     uint32_t a2, uint32_t a3,
                                     uint32_t b0, uint32_t b1) {
    asm volatile("mma.sync.aligned.m16n8k8.row.col.f32.tf32.tf32.f32 "
        "{%0,%1,%2,%3}, {%4,%5,%6,%7}, {%8,%9}, {%0,%1,%2,%3};"
        : "+f"(c[0]), "+f"(c[1]), "+f"(c[2]), "+f"(c[3])
        : "r"(a0), "r"(a1), "r"(a2), "r"(a3), "r"(b0), "r"(b1));
}
__device__ __forceinline__ void cp16(uint32_t dst, const void* src) {
    asm volatile("cp.async.cg.shared.global [%0], [%1], 16;" :: "r"(dst), "l"(src));
}
#define CP_COMMIT() asm volatile("cp.async.commit_group;")
#define CP_WAIT(n)  asm volatile("cp.async.wait_group %0;" :: "n"(n))

// ---------------- rmsnorm stage 1 ----------------
__global__ void rmsnorm_kernel(const float* __restrict__ in,
                               const float* __restrict__ w,
                               float* __restrict__ out) {
    int t = blockIdx.x;
    const float* x = in + (size_t)t * H_;
    __shared__ float red[256];
    float ss = 0.f;
    for (int i = threadIdx.x; i < H_; i += 256) { float v = x[i]; ss += v * v; }
    red[threadIdx.x] = ss; __syncthreads();
    for (int s = 128; s > 0; s >>= 1) {
        if (threadIdx.x < s) red[threadIdx.x] += red[threadIdx.x + s];
        __syncthreads();
    }
    float r = rsqrtf(red[0] / (float)H_ + EPS_);
    for (int i = threadIdx.x; i < H_; i += 256)
        out[(size_t)t * H_ + i] = roundtf(x[i] * w[i] * r);
}

// ---------------- unified tf32 GEMM, 4-stage cp.async, split-K --------------
// MODE 0: raw partial (qkv / o-proj)    grid (N/128, M/128, SPLIT)
// MODE 2: +bias swiglu round -> act     grid (N/128, 8, E), A = gathered xg
// MODE 3: raw partial, expert-tiled     grid (N/128, 8, E*SPLIT)
#define ALD 20
#define BLD 136
template<int MODE, int SPLIT>
__global__ __launch_bounds__(256) void gemm_tf32(
    const float* __restrict__ A, const float* __restrict__ Bw,
    const float* __restrict__ bias,
    float* __restrict__ C, int K, int N, int partStride,
    const int* __restrict__ eoff, const int* __restrict__ ecnt) {
    __shared__ uint32_t As[4][128][ALD];
    __shared__ uint32_t Bs[4][16][BLD];
    int tid = threadIdx.x, lane = tid & 31, wid = tid >> 5;
    int n0 = blockIdx.x * 128;
    int m0, split;
    if (MODE >= 2) {
        int e = blockIdx.z / SPLIT;
        split = blockIdx.z % SPLIT;
        if ((int)blockIdx.y * 128 >= ecnt[e]) return;
        m0 = eoff[e] + blockIdx.y * 128;
        Bw += (size_t)e * K * N;
        if (MODE == 2) bias += (size_t)e * N;
    } else {
        split = blockIdx.z;
        m0 = blockIdx.y * 128;
    }
    int Ksub = K / SPLIT;
    int kbase = split * Ksub;
    C += (size_t)split * partStride;
    int wm = (wid >> 2) * 64, wn = (wid & 3) * 32;

    uint32_t a_base = (uint32_t)__cvta_generic_to_shared(&As[0][0][0]);
    uint32_t b_base = (uint32_t)__cvta_generic_to_shared(&Bs[0][0][0]);
    int arow0 = tid >> 1, ac0 = (tid & 1) * 2;
    int brow0 = tid >> 4, bc0 = tid & 15;

    float acc[16][4];
    #pragma unroll
    for (int i = 0; i < 16; i++)
        #pragma unroll
        for (int j = 0; j < 4; j++) acc[i][j] = 0.f;

    int nchunks = Ksub / 16;
    auto issue = [&](int c, int s) {
        int k0 = kbase + c * 16;
        #pragma unroll
        for (int l = 0; l < 2; l++) {
            int c4 = ac0 + l;
            cp16(a_base + (((s * 128 + arow0) * ALD) + c4 * 4) * 4,
                 &A[(size_t)(m0 + arow0) * K + k0 + c4 * 4]);
        }
        #pragma unroll
        for (int l = 0; l < 2; l++) {
            int cc = bc0 * 2 + l;
            cp16(b_base + (((s * 16 + brow0) * BLD) + cc * 4) * 4,
                 &Bw[(size_t)(k0 + brow0) * N + n0 + cc * 4]);
        }
        CP_COMMIT();
    };

    issue(0, 0); issue(1, 1); issue(2, 2);
    for (int c = 0; c < nchunks; c++) {
        CP_WAIT(2);
        __syncthreads();
        if (c + 3 < nchunks) issue(c + 3, (c + 3) & 3); else CP_COMMIT();
        int s = c & 3;
        // hoist ALL B-fragment loads + cvts for both ks-steps (16 independent LDS)
        uint32_t bb[2][4][2];
        #pragma unroll
        for (int ks = 0; ks < 2; ks++) {
            int kq = ks * 8 + (lane & 3);
            #pragma unroll
            for (int ni = 0; ni < 4; ni++) {
                int n = wn + ni * 8 + (lane >> 2);
                bb[ks][ni][0] = f2tf_bits(Bs[s][kq][n]);
                bb[ks][ni][1] = f2tf_bits(Bs[s][kq + 4][n]);
            }
        }
        #pragma unroll
        for (int ks = 0; ks < 2; ks++) {
            int kq = ks * 8 + (lane & 3);
            #pragma unroll
            for (int mi = 0; mi < 4; mi++) {
                int m = wm + mi * 16 + (lane >> 2);
                uint32_t a0 = As[s][m][kq];
                uint32_t a1 = As[s][m + 8][kq];
                uint32_t a2 = As[s][m][kq + 4];
                uint32_t a3 = As[s][m + 8][kq + 4];
                #pragma unroll
                for (int ni = 0; ni < 4; ni++)
                    mma8(acc[mi * 4 + ni], a0, a1, a2, a3,
                         bb[ks][ni][0], bb[ks][ni][1]);
            }
        }
        __syncthreads();
    }
    #pragma unroll
    for (int mi = 0; mi < 4; mi++) {
        #pragma unroll
        for (int ni = 0; ni < 4; ni++) {
            float* cc = acc[mi * 4 + ni];
            int row = m0 + wm + mi * 16 + (lane >> 2);
            int col = n0 + wn + ni * 8 + 2 * (lane & 3);
            #pragma unroll
            for (int h = 0; h < 2; h++) {
                int r = row + h * 8;
                float v0 = cc[h * 2 + 0];
                float v1 = cc[h * 2 + 1];
                if (MODE == 2) {
                    float g = fminf(v0 + bias[col], LIMIT_);
                    float u = fminf(fmaxf(v1 + bias[col + 1], -LIMIT_), LIMIT_);
                    float glu = g / (1.f + expf(-g * ALPHA_));
                    C[(size_t)r * (N >> 1) + (col >> 1)] = roundtf((u + 1.f) * glu);
                } else {
                    *(float2*)&C[(size_t)r * N + col] = make_float2(v0, v1);
                }
            }
        }
    }
}

// ---------------- tensor-core sliding-window attention (2 qkv partials) ------
#define QLD 68
#define KVLD 72
#define PLD 148
#define ATT_SMEM ((64 * QLD + 2 * 144 * KVLD + 64 * PLD + 64) * 4)
__global__ void attn_mma(const float* __restrict__ qkvp,
                         const float* __restrict__ bqkv,
                         const float* __restrict__ kvc,
                         const int* __restrict__ pidx,
                         const float* __restrict__ sinks,
                         float* __restrict__ attn) {
    extern __shared__ float sm[];
    float* Qs = sm;
    float* Ks = Qs + 64 * QLD;
    float* Vs = Ks + 144 * KVLD;
    float* Ps = Vs + 144 * KVLD;
    float* dinv = Ps + 64 * PLD;
    int qt = blockIdx.x, kv = blockIdx.y, b = blockIdx.z;
    int tid = threadIdx.x, lane = tid & 31, wid = tid >> 5;
    int qpos0 = S_ - Q_ + qt * 16;
    int base = qpos0 - (SW_ - 1);

    #pragma unroll
    for (int l = 0; l < 4; l++) {
        int f = tid + 256 * l;
        int r = f >> 4, d4 = f & 15;
        int ql = r >> 2, g = r & 3;
        size_t o = (size_t)(b * Q_ + qt * 16 + ql) * QKVD + (kv * G_ + g) * HD_ + d4 * 4;
        float4 acc = *(const float4*)&bqkv[(kv * G_ + g) * HD_ + d4 * 4];
        #pragma unroll
        for (int j = 0; j < QKV_SPLIT; j++) {
            float4 a = *(const float4*)&qkvp[(size_t)j * T_ * QKVD + o];
            acc.x += a.x; acc.y += a.y; acc.z += a.z; acc.w += a.w;
        }
        Qs[r * QLD + d4 * 4 + 0] = roundtf(acc.x * SCALE_);
        Qs[r * QLD + d4 * 4 + 1] = roundtf(acc.y * SCALE_);
        Qs[r * QLD + d4 * 4 + 2] = roundtf(acc.z * SCALE_);
        Qs[r * QLD + d4 * 4 + 3] = roundtf(acc.w * SCALE_);
    }
    for (int f = tid; f < 143 * 16; f += 256) {
        int k = f >> 4, d4 = f & 15;
        int kpos = base + k;
        float4 kf, vf;
        if (kpos < S_ - Q_) {
            int page = pidx[b * P_ + (kpos >> 7)];
            size_t o = (((size_t)page * 2) * PS_ + (kpos & 127)) * NKV_ + kv;
            kf = *(const float4*)&kvc[o * HD_ + d4 * 4];
            vf = *(const float4*)&kvc[(o + (size_t)PS_ * NKV_) * HD_ + d4 * 4];
        } else {
            size_t t = (size_t)(b * Q_ + kpos - (S_ - Q_)) * QKVD;
            int ck = NQ_ * HD_ + kv * HD_ + d4 * 4;
            int cv = (NQ_ + NKV_) * HD_ + kv * HD_ + d4 * 4;
            kf = *(const float4*)&bqkv[ck];
            vf = *(const float4*)&bqkv[cv];
            #pragma unroll
            for (int j = 0; j < QKV_SPLIT; j++) {
                float4 a = *(const float4*)&qkvp[(size_t)j * T_ * QKVD + t + ck];
                kf.x += a.x; kf.y += a.y; kf.z += a.z; kf.w += a.w;
                float4 c = *(const float4*)&qkvp[(size_t)j * T_ * QKVD + t + cv];
                vf.x += c.x; vf.y += c.y; vf.z += c.z; vf.w += c.w;
            }
        }
        *(float4*)&Ks[k * KVLD + d4 * 4] = kf;
        *(float4*)&Vs[k * KVLD + d4 * 4] = vf;
    }
    if (tid < 32) {
        int d4 = tid & 15;
        if (tid < 16) *(float4*)&Ks[143 * KVLD + d4 * 4] = make_float4(0, 0, 0, 0);
        else          *(float4*)&Vs[143 * KVLD + d4 * 4] = make_float4(0, 0, 0, 0);
    }
    __syncthreads();

    int mt = wid & 3, nh = wid >> 2;
    int r0 = mt * 16 + (lane >> 2);
    {
        float sacc[9][4];
        #pragma unroll
        for (int i = 0; i < 9; i++)
            #pragma unroll
            for (int j = 0; j < 4; j++) sacc[i][j] = 0.f;
        #pragma unroll
        for (int kk = 0; kk < 8; kk++) {
            int kq = kk * 8 + (lane & 3);
            uint32_t a0 = __float_as_uint(Qs[r0 * QLD + kq]);
            uint32_t a1 = __float_as_uint(Qs[(r0 + 8) * QLD + kq]);
            uint32_t a2 = __float_as_uint(Qs[r0 * QLD + kq + 4]);
            uint32_t a3 = __float_as_uint(Qs[(r0 + 8) * QLD + kq + 4]);
            #pragma unroll
            for (int ni = 0; ni < 9; ni++) {
                int n = nh * 72 + ni * 8 + (lane >> 2);
                uint32_t b0 = f2tf_bits(__float_as_uint(Ks[n * KVLD + kq]));
                uint32_t b1 = f2tf_bits(__float_as_uint(Ks[n * KVLD + kq + 4]));
                mma8(sacc[ni], a0, a1, a2, a3, b0, b1);
            }
        }
        #pragma unroll
        for (int ni = 0; ni < 9; ni++) {
            #pragma unroll
            for (int h = 0; h < 2; h++) {
                int row = r0 + h * 8;
                int ql = row >> 2;
                int cb = nh * 72 + ni * 8 + 2 * (lane & 3);
                float v0 = sacc[ni][h * 2 + 0];
                float v1 = sacc[ni][h * 2 + 1];
                if (cb < ql || cb > ql + 127) v0 = -1e30f;
                if (cb + 1 < ql || cb + 1 > ql + 127) v1 = -1e30f;
                Ps[row * PLD + cb] = v0;
                Ps[row * PLD + cb + 1] = v1;
            }
        }
    }
    __syncthreads();
    {
        int row = tid >> 2, part = tid & 3;
        float mx = -1e30f;
        #pragma unroll 4
        for (int j = 0; j < 36; j++)
            mx = fmaxf(mx, Ps[row * PLD + part * 36 + j]);
        mx = fmaxf(mx, __shfl_xor_sync(0xffffffffu, mx, 1));
        mx = fmaxf(mx, __shfl_xor_sync(0xffffffffu, mx, 2));
        float sum = 0.f;
        #pragma unroll 4
        for (int j = 0; j < 36; j++) {
            float p = expf(Ps[row * PLD + part * 36 + j] - mx);
            Ps[row * PLD + part * 36 + j] = roundtf(p);
            sum += p;
        }
        sum += __shfl_xor_sync(0xffffffffu, sum, 1);
        sum += __shfl_xor_sync(0xffffffffu, sum, 2);
        if (part == 0)
            dinv[row] = 1.f / (sum + expf(sinks[kv * G_ + (row & 3)] - mx));
    }
    __syncthreads();
    {
        float oacc[4][4];
        #pragma unroll
        for (int i = 0; i < 4; i++)
            #pragma unroll
            for (int j = 0; j < 4; j++) oacc[i][j] = 0.f;
        #pragma unroll 2
        for (int kk = 0; kk < 18; kk++) {
            int kq = kk * 8 + (lane & 3);
            uint32_t a0 = __float_as_uint(Ps[r0 * PLD + kq]);
            uint32_t a1 = __float_as_uint(Ps[(r0 + 8) * PLD + kq]);
            uint32_t a2 = __float_as_uint(Ps[r0 * PLD + kq + 4]);
            uint32_t a3 = __float_as_uint(Ps[(r0 + 8) * PLD + kq + 4]);
            #pragma unroll
            for (int ni = 0; ni < 4; ni++) {
                int n = nh * 32 + ni * 8 + (lane >> 2);
                uint32_t b0 = f2tf_bits(__float_as_uint(Vs[kq * KVLD + n]));
                uint32_t b1 = f2tf_bits(__float_as_uint(Vs[(kq + 4) * KVLD + n]));
                mma8(oacc[ni], a0, a1, a2, a3, b0, b1);
            }
        }
        #pragma unroll
        for (int ni = 0; ni < 4; ni++) {
            #pragma unroll
            for (int h = 0; h < 2; h++) {
                int row = r0 + h * 8;
                float di = dinv[row];
                int t = b * Q_ + qt * 16 + (row >> 2);
                int head = kv * G_ + (row & 3);
                int col = nh * 32 + ni * 8 + 2 * (lane & 3);
                float2 o;
                o.x = roundtf(oacc[ni][h * 2 + 0] * di);
                o.y = roundtf(oacc[ni][h * 2 + 1] * di);
                *(float2*)&attn[(size_t)t * (NQ_ * HD_) + head * HD_ + col] = o;
            }
        }
    }
}

// ---------------- out reduce (o-proj partials + residual + bias) ----------------
__global__ void out_reduce(const float* __restrict__ p,
                           const float* __restrict__ hidden,
                           const float* __restrict__ bias,
                           float* __restrict__ out) {
    int t = blockIdx.x, i = threadIdx.x;
    const float4* hh = (const float4*)(hidden + (size_t)t * H_);
    const float4* bb = (const float4*)bias;
    float4 r = hh[i], c = bb[i];
    r.x += c.x; r.y += c.y; r.z += c.z; r.w += c.w;
    #pragma unroll
    for (int s = 0; s < OPJ_SPLIT; s++) {
        float4 a = ((const float4*)(p + (size_t)(s * T_ + t) * H_))[i];
        r.x += a.x; r.y += a.y; r.z += a.z; r.w += a.w;
    }
    ((float4*)(out + (size_t)t * H_))[i] = r;
}

// ---------------- fused rmsnorm2 + router ----------------
__global__ void rms_router(const float* __restrict__ in,
                           const float* __restrict__ w,
                           const float* __restrict__ wr,
                           const float* __restrict__ br,
                           float* __restrict__ x2,
                           int* __restrict__ eidx, float* __restrict__ ewt) {
    int t = blockIdx.x, tid = threadIdx.x;
    const float* x = in + (size_t)t * H_;
    __shared__ float red[256];
    __shared__ float lac[256][E_];
    float ss = 0.f;
    for (int i = tid; i < H_; i += 256) { float v = x[i]; ss += v * v; }
    red[tid] = ss; __syncthreads();
    for (int s = 128; s > 0; s >>= 1) {
        if (tid < s) red[tid] += red[tid + s];
        __syncthreads();
    }
    float r = rsqrtf(red[0] / (float)H_ + EPS_);
    float acc[E_];
    #pragma unroll
    for (int e = 0; e < E_; e++) acc[e] = 0.f;
    for (int i = tid; i < H_; i += 256) {
        float v = x[i] * w[i] * r;
        x2[(size_t)t * H_ + i] = v;
        #pragma unroll
        for (int e = 0; e < E_; e++) acc[e] += v * wr[i * E_ + e];
    }
    #pragma unroll
    for (int e = 0; e < E_; e++) lac[tid][e] = acc[e];
    __syncthreads();
    for (int s = 128; s > 0; s >>= 1) {
        if (tid < s)
            #pragma unroll
            for (int e = 0; e < E_; e++) lac[tid][e] += lac[tid + s][e];
        __syncthreads();
    }
    if (tid == 0) {
        float l[E_];
        #pragma unroll
        for (int e = 0; e < E_; e++) l[e] = lac[0][e] + br[e];
        int i0 = 0; float v0 = l[0];
        #pragma unroll
        for (int e = 1; e < E_; e++) if (l[e] > v0) { v0 = l[e]; i0 = e; }
        int i1 = -1; float v1 = -1e30f;
        #pragma unroll
        for (int e = 0; e < E_; e++)
            if (e != i0 && l[e] > v1) { v1 = l[e]; i1 = e; }
        float e1 = expf(v1 - v0);
        float inv = 1.f / (1.f + e1);
        eidx[t * 2 + 0] = i0; eidx[t * 2 + 1] = i1;
        ewt[t * 2 + 0] = inv; ewt[t * 2 + 1] = e1 * inv;
    }
}

// ---------------- route sort ----------------
__global__ void route_sort_kernel(const int* __restrict__ eidx,
                                  int* __restrict__ eoff, int* __restrict__ ecnt,
                                  int* __restrict__ tokof, int* __restrict__ slotmap) {
    __shared__ int cnt[E_];
    __shared__ int pos[E_];
    int tid = threadIdx.x;
    if (tid < E_) cnt[tid] = 0;
    for (int i = tid; i < NAPAD; i += 256) tokof[i] = -1;
    __syncthreads();
    for (int a = tid; a < T_ * 2; a += 256) atomicAdd(&cnt[eidx[a]], 1);
    __syncthreads();
    if (tid == 0) {
        int off = 0;
        for (int e = 0; e < E_; e++) {
            eoff[e] = off; ecnt[e] = cnt[e]; pos[e] = off;
            off += ((cnt[e] + 127) / 128) * 128;
        }
    }
    __syncthreads();
    for (int a = tid; a < T_ * 2; a += 256) {
        int e = eidx[a];
        int slot = atomicAdd(&pos[e], 1);
        tokof[slot] = a;
        slotmap[a] = slot;
    }
}

// ---------------- gather (rounds to tf32 for GEMM A) ----------------
__global__ void gather_kernel(const float* __restrict__ x2,
                              const int* __restrict__ tokof,
                              float* __restrict__ xg) {
    int slot = blockIdx.x;
    int a = tokof[slot];
    float4* dst = (float4*)(xg + (size_t)slot * H_);
    if (a < 0) {
        dst[threadIdx.x] = make_float4(0.f, 0.f, 0.f, 0.f);
    } else {
        float4 v = ((const float4*)(x2 + (size_t)(a >> 1) * H_))[threadIdx.x];
        v.x = roundtf(v.x); v.y = roundtf(v.y);
        v.z = roundtf(v.z); v.w = roundtf(v.w);
        dst[threadIdx.x] = v;
    }
}

// ---------------- combine ----------------
__global__ void combine_kernel(const float* __restrict__ eop,
                               const int* __restrict__ slotmap,
                               const int* __restrict__ eidx,
                               const float* __restrict__ ewt,
                               const float* __restrict__ bd,
                               float* __restrict__ out) {
    int t = blockIdx.x, i = threadIdx.x;
    float4 o = ((float4*)(out + (size_t)t * H_))[i];
    #pragma unroll
    for (int ei = 0; ei < 2; ei++) {
        int s = slotmap[t * 2 + ei];
        int e = eidx[t * 2 + ei];
        float w = ewt[t * 2 + ei];
        float4 a = ((const float4*)(bd + (size_t)e * H_))[i];
        #pragma unroll
        for (int sp = 0; sp < DN_SPLIT; sp++) {
            float4 b = ((const float4*)(eop + (size_t)(sp * NAPAD + s) * H_))[i];
            a.x += b.x; a.y += b.y; a.z += b.z; a.w += b.w;
        }
        o.x += w * a.x; o.y += w * a.y; o.z += w * a.z; o.w += w * a.w;
    }
    ((float4*)(out + (size_t)t * H_))[i] = o;
}

// ---------------- launch ----------------
extern "C" void kernel_launch(void* const* d_in, const int* in_sizes, int n_in,
                              void* d_out, int out_size) {
    const float* hidden = (const float*)d_in[0];
    const float* kvc    = (const float*)d_in[1];
    const int*   pidx   = (const int*)d_in[3];
    const float* sinks  = (const float*)d_in[4];
    const float* w_qkv  = (const float*)d_in[5];
    const float* b_qkv  = (const float*)d_in[6];
    const float* w_o    = (const float*)d_in[7];
    const float* b_o    = (const float*)d_in[8];
    const float* ln1    = (const float*)d_in[9];
    const float* ln2    = (const float*)d_in[10];
    const float* w_r    = (const float*)d_in[11];
    const float* b_r    = (const float*)d_in[12];
    const float* w_gu   = (const float*)d_in[13];
    const float* b_gu   = (const float*)d_in[14];
    const float* w_d    = (const float*)d_in[15];
    const float* b_d    = (const float*)d_in[16];
    float* out = (float*)d_out;

    float *px, *pqkvp, *pattn, *poutp, *px2, *pewt, *pxg, *pact, *peop;
    int *peidx, *peoff, *pecnt, *ptokof, *pslot;
    cudaGetSymbolAddress((void**)&px,     g_x);
    cudaGetSymbolAddress((void**)&pqkvp,  g_qkvp);
    cudaGetSymbolAddress((void**)&pattn,  g_attn);
    cudaGetSymbolAddress((void**)&poutp,  g_outp);
    cudaGetSymbolAddress((void**)&px2,    g_x2);
    cudaGetSymbolAddress((void**)&peidx,  g_eidx);
    cudaGetSymbolAddress((void**)&pewt,   g_ewt);
    cudaGetSymbolAddress((void**)&peoff,  g_eoff);
    cudaGetSymbolAddress((void**)&pecnt,  g_ecnt);
    cudaGetSymbolAddress((void**)&ptokof, g_tokof);
    cudaGetSymbolAddress((void**)&pslot,  g_slotmap);
    cudaGetSymbolAddress((void**)&pxg,    g_xg);
    cudaGetSymbolAddress((void**)&pact,   g_act);
    cudaGetSymbolAddress((void**)&peop,   g_eop);

    cudaFuncSetAttribute(attn_mma,
                         cudaFuncAttributeMaxDynamicSharedMemorySize, ATT_SMEM);

    rmsnorm_kernel<<<T_, 256>>>(hidden, ln1, px);
    gemm_tf32<0, QKV_SPLIT><<<dim3(QKVD / 128, T_ / 128, QKV_SPLIT), 256>>>(
        px, w_qkv, nullptr, pqkvp, H_, QKVD, T_ * QKVD, nullptr, nullptr);
    attn_mma<<<dim3(Q_ / 16, NKV_, B_), 256, ATT_SMEM>>>(
        pqkvp, b_qkv, kvc, pidx, sinks, pattn);
    gemm_tf32<0, OPJ_SPLIT><<<dim3(H_ / 128, T_ / 128, OPJ_SPLIT), 256>>>(
        pattn, w_o, nullptr, poutp, H_, H_, T_ * H_, nullptr, nullptr);
    out_reduce<<<T_, 256>>>(poutp, hidden, b_o, out);
    rms_router<<<T_, 256>>>(out, ln2, w_r, b_r, px2, peidx, pewt);
    route_sort_kernel<<<1, 256>>>(peidx, peoff, pecnt, ptokof, pslot);
    gather_kernel<<<NAPAD, 256>>>(px2, ptokof, pxg);
    gemm_tf32<2, 1><<<dim3(2 * FFN_ / 128, 8, E_), 256>>>(
        pxg, w_gu, b_gu, pact, H_, 2 * FFN_, 0, peoff, pecnt);
    gemm_tf32<3, DN_SPLIT><<<dim3(H_ / 128, 8, E_ * DN_SPLIT), 256>>>(
        pact, w_d, nullptr, peop, FFN_, H_, NAPAD * H_, peoff, pecnt);
    combine_kernel<<<T_, 256>>>(peop, pslot, peidx, pewt, b_d, out);
}

// round 15
// speedup vs baseline: 1.6377x; 1.1400x over previous
#include <cuda_runtime.h>
#include <cstdint>
#include <math.h>

#define T_    512
#define H_    1024
#define HD_   64
#define NQ_   16
#define NKV_  4
#define G_    4
#define E_    8
#define FFN_  1024
#define B_    4
#define Q_    128
#define P_    8
#define PS_   128
#define S_    1024
#define SW_   128
#define QKVD  1536
#define SCALE_ 0.125f
#define ALPHA_ 1.702f
#define LIMIT_ 7.0f
#define EPS_   1e-5f
#define NAPAD 2048

#define QKV_SPLIT 2
#define OPJ_SPLIT 4
#define DN_SPLIT  2

// ---------------- scratch ----------------
__device__ float g_x[T_ * H_];
__device__ float g_qkvp[QKV_SPLIT * T_ * QKVD];
__device__ float g_attn[T_ * NQ_ * HD_];
__device__ float g_outp[OPJ_SPLIT * T_ * H_];
__device__ float g_x2[T_ * H_];
__device__ int   g_eidx[T_ * 2];
__device__ float g_ewt[T_ * 2];
__device__ int   g_eoff[E_];
__device__ int   g_ecnt[E_];
__device__ int   g_tokof[NAPAD];
__device__ int   g_slotmap[T_ * 2];
__device__ float g_xg[NAPAD * H_];
__device__ float g_act[NAPAD * FFN_];
__device__ float g_eop[DN_SPLIT * NAPAD * H_];

// ---------------- helpers ----------------
__device__ __forceinline__ uint32_t f2tf_bits(uint32_t bits) {
    uint32_t r;
    asm("cvt.rna.tf32.f32 %0, %1;" : "=r"(r) : "f"(__uint_as_float(bits)));
    return r;
}
__device__ __forceinline__ float roundtf(float f) {
    uint32_t r;
    asm("cvt.rna.tf32.f32 %0, %1;" : "=r"(r) : "f"(f));
    return __uint_as_float(r);
}
__device__ __forceinline__ uint32_t pack_h2(float lo, float hi) {
    uint32_t r;
    asm("cvt.rn.f16x2.f32 %0, %1, %2;" : "=r"(r) : "f"(hi), "f"(lo));
    return r;
}
__device__ __forceinline__ void mma8(float* c, uint32_t a0, uint32_t a1,
                                     uint32_t a2, uint32_t a3,
                                     uint32_t b0, uint32_t b1) {
    asm volatile("mma.sync.aligned.m16n8k8.row.col.f32.tf32.tf32.f32 "
        "{%0,%1,%2,%3}, {%4,%5,%6,%7}, {%8,%9}, {%0,%1,%2,%3};"
        : "+f"(c[0]), "+f"(c[1]), "+f"(c[2]), "+f"(c[3])
        : "r"(a0), "r"(a1), "r"(a2), "r"(a3), "r"(b0), "r"(b1));
}
__device__ __forceinline__ void mma16(float* c, uint32_t a0, uint32_t a1,
                                      uint32_t a2, uint32_t a3,
                                      uint32_t b0, uint32_t b1) {
    asm volatile("mma.sync.aligned.m16n8k16.row.col.f32.f16.f16.f32 "
        "{%0,%1,%2,%3}, {%4,%5,%6,%7}, {%8,%9}, {%0,%1,%2,%3};"
        : "+f"(c[0]), "+f"(c[1]), "+f"(c[2]), "+f"(c[3])
        : "r"(a0), "r"(a1), "r"(a2), "r"(a3), "r"(b0), "r"(b1));
}
__device__ __forceinline__ void cp16(uint32_t dst, const void* src) {
    asm volatile("cp.async.cg.shared.global [%0], [%1], 16;" :: "r"(dst), "l"(src));
}
#define CP_COMMIT() asm volatile("cp.async.commit_group;")
#define CP_WAIT(n)  asm volatile("cp.async.wait_group %0;" :: "n"(n))

// ---------------- rmsnorm stage 1 ----------------
__global__ void rmsnorm_kernel(const float* __restrict__ in,
                               const float* __restrict__ w,
                               float* __restrict__ out) {
    int t = blockIdx.x;
    const float* x = in + (size_t)t * H_;
    __shared__ float red[256];
    float ss = 0.f;
    for (int i = threadIdx.x; i < H_; i += 256) { float v = x[i]; ss += v * v; }
    red[threadIdx.x] = ss; __syncthreads();
    for (int s = 128; s > 0; s >>= 1) {
        if (threadIdx.x < s) red[threadIdx.x] += red[threadIdx.x + s];
        __syncthreads();
    }
    float r = rsqrtf(red[0] / (float)H_ + EPS_);
    for (int i = threadIdx.x; i < H_; i += 256)
        out[(size_t)t * H_ + i] = roundtf(x[i] * w[i] * r);
}

// ------- unified fp16 tensor GEMM (m16n8k16), 4-stage cp.async, split-K -----
// MODE 0: raw partial   MODE 2: +bias swiglu -> act   MODE 3: raw partial expert
#define ALD 24
#define BLD 140
#define GEMM_SMEM ((4 * 128 * ALD + 4 * 16 * BLD) * 4)
template<int MODE, int SPLIT>
__global__ __launch_bounds__(256) void gemm_h16(
    const float* __restrict__ A, const float* __restrict__ Bw,
    const float* __restrict__ bias,
    float* __restrict__ C, int K, int N, int partStride,
    const int* __restrict__ eoff, const int* __restrict__ ecnt) {
    extern __shared__ float gsmf[];
    float* Asm = gsmf;                     // [4][128][ALD]
    float* Bsm = gsmf + 4 * 128 * ALD;     // [4][16][BLD]
    int tid = threadIdx.x, lane = tid & 31, wid = tid >> 5;
    int n0 = blockIdx.x * 128;
    int m0, split;
    if (MODE >= 2) {
        int e = blockIdx.z / SPLIT;
        split = blockIdx.z % SPLIT;
        if ((int)blockIdx.y * 128 >= ecnt[e]) return;
        m0 = eoff[e] + blockIdx.y * 128;
        Bw += (size_t)e * K * N;
        if (MODE == 2) bias += (size_t)e * N;
    } else {
        split = blockIdx.z;
        m0 = blockIdx.y * 128;
    }
    int Ksub = K / SPLIT;
    int kbase = split * Ksub;
    C += (size_t)split * partStride;
    int wm = (wid >> 2) * 64, wn = (wid & 3) * 32;

    uint32_t a_base = (uint32_t)__cvta_generic_to_shared(Asm);
    uint32_t b_base = (uint32_t)__cvta_generic_to_shared(Bsm);
    int arow0 = tid >> 1, ac0 = (tid & 1) * 2;
    int brow0 = tid >> 4, bc0 = tid & 15;

    float acc[16][4];
    #pragma unroll
    for (int i = 0; i < 16; i++)
        #pragma unroll
        for (int j = 0; j < 4; j++) acc[i][j] = 0.f;

    int nchunks = Ksub / 16;
    auto issue = [&](int c, int s) {
        int k0 = kbase + c * 16;
        #pragma unroll
        for (int l = 0; l < 2; l++) {
            int c4 = ac0 + l;
            cp16(a_base + (((s * 128 + arow0) * ALD) + c4 * 4) * 4,
                 &A[(size_t)(m0 + arow0) * K + k0 + c4 * 4]);
        }
        #pragma unroll
        for (int l = 0; l < 2; l++) {
            int cc = bc0 * 2 + l;
            cp16(b_base + (((s * 16 + brow0) * BLD) + cc * 4) * 4,
                 &Bw[(size_t)(k0 + brow0) * N + n0 + cc * 4]);
        }
        CP_COMMIT();
    };

    int g = lane >> 2, kq = (lane & 3) * 2;
    issue(0, 0); issue(1, 1); issue(2, 2);
    for (int c = 0; c < nchunks; c++) {
        CP_WAIT(2);
        __syncthreads();
        if (c + 3 < nchunks) issue(c + 3, (c + 3) & 3); else CP_COMMIT();
        int s = c & 3;
        const float* Ab = Asm + s * 128 * ALD;
        const float* Bb = Bsm + s * 16 * BLD;
        uint32_t bf[4][2];
        #pragma unroll
        for (int ni = 0; ni < 4; ni++) {
            int n = wn + ni * 8 + g;
            bf[ni][0] = pack_h2(Bb[kq * BLD + n], Bb[(kq + 1) * BLD + n]);
            bf[ni][1] = pack_h2(Bb[(kq + 8) * BLD + n], Bb[(kq + 9) * BLD + n]);
        }
        #pragma unroll
        for (int mi = 0; mi < 4; mi++) {
            int m = wm + mi * 16 + g;
            float2 p0 = *(const float2*)&Ab[m * ALD + kq];
            float2 p1 = *(const float2*)&Ab[(m + 8) * ALD + kq];
            float2 p2 = *(const float2*)&Ab[m * ALD + kq + 8];
            float2 p3 = *(const float2*)&Ab[(m + 8) * ALD + kq + 8];
            uint32_t a0 = pack_h2(p0.x, p0.y);
            uint32_t a1 = pack_h2(p1.x, p1.y);
            uint32_t a2 = pack_h2(p2.x, p2.y);
            uint32_t a3 = pack_h2(p3.x, p3.y);
            #pragma unroll
            for (int ni = 0; ni < 4; ni++)
                mma16(acc[mi * 4 + ni], a0, a1, a2, a3, bf[ni][0], bf[ni][1]);
        }
        __syncthreads();
    }
    #pragma unroll
    for (int mi = 0; mi < 4; mi++) {
        #pragma unroll
        for (int ni = 0; ni < 4; ni++) {
            float* cc = acc[mi * 4 + ni];
            int row = m0 + wm + mi * 16 + g;
            int col = n0 + wn + ni * 8 + 2 * (lane & 3);
            #pragma unroll
            for (int h = 0; h < 2; h++) {
                int r = row + h * 8;
                float v0 = cc[h * 2 + 0];
                float v1 = cc[h * 2 + 1];
                if (MODE == 2) {
                    float gg = fminf(v0 + bias[col], LIMIT_);
                    float u = fminf(fmaxf(v1 + bias[col + 1], -LIMIT_), LIMIT_);
                    float glu = gg / (1.f + expf(-gg * ALPHA_));
                    C[(size_t)r * (N >> 1) + (col >> 1)] = roundtf((u + 1.f) * glu);
                } else {
                    *(float2*)&C[(size_t)r * N + col] = make_float2(v0, v1);
                }
            }
        }
    }
}

// ---------------- tensor-core sliding-window attention (2 qkv partials) ------
#define QLD 68
#define KVLD 72
#define PLD 148
#define ATT_SMEM ((64 * QLD + 2 * 144 * KVLD + 64 * PLD + 64) * 4)
__global__ void attn_mma(const float* __restrict__ qkvp,
                         const float* __restrict__ bqkv,
                         const float* __restrict__ kvc,
                         const int* __restrict__ pidx,
                         const float* __restrict__ sinks,
                         float* __restrict__ attn) {
    extern __shared__ float sm[];
    float* Qs = sm;
    float* Ks = Qs + 64 * QLD;
    float* Vs = Ks + 144 * KVLD;
    float* Ps = Vs + 144 * KVLD;
    float* dinv = Ps + 64 * PLD;
    int qt = blockIdx.x, kv = blockIdx.y, b = blockIdx.z;
    int tid = threadIdx.x, lane = tid & 31, wid = tid >> 5;
    int qpos0 = S_ - Q_ + qt * 16;
    int base = qpos0 - (SW_ - 1);

    #pragma unroll
    for (int l = 0; l < 4; l++) {
        int f = tid + 256 * l;
        int r = f >> 4, d4 = f & 15;
        int ql = r >> 2, g = r & 3;
        size_t o = (size_t)(b * Q_ + qt * 16 + ql) * QKVD + (kv * G_ + g) * HD_ + d4 * 4;
        float4 acc = *(const float4*)&bqkv[(kv * G_ + g) * HD_ + d4 * 4];
        #pragma unroll
        for (int j = 0; j < QKV_SPLIT; j++) {
            float4 a = *(const float4*)&qkvp[(size_t)j * T_ * QKVD + o];
            acc.x += a.x; acc.y += a.y; acc.z += a.z; acc.w += a.w;
        }
        Qs[r * QLD + d4 * 4 + 0] = roundtf(acc.x * SCALE_);
        Qs[r * QLD + d4 * 4 + 1] = roundtf(acc.y * SCALE_);
        Qs[r * QLD + d4 * 4 + 2] = roundtf(acc.z * SCALE_);
        Qs[r * QLD + d4 * 4 + 3] = roundtf(acc.w * SCALE_);
    }
    for (int f = tid; f < 143 * 16; f += 256) {
        int k = f >> 4, d4 = f & 15;
        int kpos = base + k;
        float4 kf, vf;
        if (kpos < S_ - Q_) {
            int page = pidx[b * P_ + (kpos >> 7)];
            size_t o = (((size_t)page * 2) * PS_ + (kpos & 127)) * NKV_ + kv;
            kf = *(const float4*)&kvc[o * HD_ + d4 * 4];
            vf = *(const float4*)&kvc[(o + (size_t)PS_ * NKV_) * HD_ + d4 * 4];
        } else {
            size_t t = (size_t)(b * Q_ + kpos - (S_ - Q_)) * QKVD;
            int ck = NQ_ * HD_ + kv * HD_ + d4 * 4;
            int cv = (NQ_ + NKV_) * HD_ + kv * HD_ + d4 * 4;
            kf = *(const float4*)&bqkv[ck];
            vf = *(const float4*)&bqkv[cv];
            #pragma unroll
            for (int j = 0; j < QKV_SPLIT; j++) {
                float4 a = *(const float4*)&qkvp[(size_t)j * T_ * QKVD + t + ck];
                kf.x += a.x; kf.y += a.y; kf.z += a.z; kf.w += a.w;
                float4 c = *(const float4*)&qkvp[(size_t)j * T_ * QKVD + t + cv];
                vf.x += c.x; vf.y += c.y; vf.z += c.z; vf.w += c.w;
            }
        }
        *(float4*)&Ks[k * KVLD + d4 * 4] = kf;
        *(float4*)&Vs[k * KVLD + d4 * 4] = vf;
    }
    if (tid < 32) {
        int d4 = tid & 15;
        if (tid < 16) *(float4*)&Ks[143 * KVLD + d4 * 4] = make_float4(0, 0, 0, 0);
        else          *(float4*)&Vs[143 * KVLD + d4 * 4] = make_float4(0, 0, 0, 0);
    }
    __syncthreads();

    int mt = wid & 3, nh = wid >> 2;
    int r0 = mt * 16 + (lane >> 2);
    {
        float sacc[9][4];
        #pragma unroll
        for (int i = 0; i < 9; i++)
            #pragma unroll
            for (int j = 0; j < 4; j++) sacc[i][j] = 0.f;
        #pragma unroll
        for (int kk = 0; kk < 8; kk++) {
            int kq = kk * 8 + (lane & 3);
            uint32_t a0 = __float_as_uint(Qs[r0 * QLD + kq]);
            uint32_t a1 = __float_as_uint(Qs[(r0 + 8) * QLD + kq]);
            uint32_t a2 = __float_as_uint(Qs[r0 * QLD + kq + 4]);
            uint32_t a3 = __float_as_uint(Qs[(r0 + 8) * QLD + kq + 4]);
            #pragma unroll
            for (int ni = 0; ni < 9; ni++) {
                int n = nh * 72 + ni * 8 + (lane >> 2);
                uint32_t b0 = f2tf_bits(__float_as_uint(Ks[n * KVLD + kq]));
                uint32_t b1 = f2tf_bits(__float_as_uint(Ks[n * KVLD + kq + 4]));
                mma8(sacc[ni], a0, a1, a2, a3, b0, b1);
            }
        }
        #pragma unroll
        for (int ni = 0; ni < 9; ni++) {
            #pragma unroll
            for (int h = 0; h < 2; h++) {
                int row = r0 + h * 8;
                int ql = row >> 2;
                int cb = nh * 72 + ni * 8 + 2 * (lane & 3);
                float v0 = sacc[ni][h * 2 + 0];
                float v1 = sacc[ni][h * 2 + 1];
                if (cb < ql || cb > ql + 127) v0 = -1e30f;
                if (cb + 1 < ql || cb + 1 > ql + 127) v1 = -1e30f;
                Ps[row * PLD + cb] = v0;
                Ps[row * PLD + cb + 1] = v1;
            }
        }
    }
    __syncthreads();
    {
        int row = tid >> 2, part = tid & 3;
        float mx = -1e30f;
        #pragma unroll 4
        for (int j = 0; j < 36; j++)
            mx = fmaxf(mx, Ps[row * PLD + part * 36 + j]);
        mx = fmaxf(mx, __shfl_xor_sync(0xffffffffu, mx, 1));
        mx = fmaxf(mx, __shfl_xor_sync(0xffffffffu, mx, 2));
        float sum = 0.f;
        #pragma unroll 4
        for (int j = 0; j < 36; j++) {
            float p = expf(Ps[row * PLD + part * 36 + j] - mx);
            Ps[row * PLD + part * 36 + j] = roundtf(p);
            sum += p;
        }
        sum += __shfl_xor_sync(0xffffffffu, sum, 1);
        sum += __shfl_xor_sync(0xffffffffu, sum, 2);
        if (part == 0)
            dinv[row] = 1.f / (sum + expf(sinks[kv * G_ + (row & 3)] - mx));
    }
    __syncthreads();
    {
        float oacc[4][4];
        #pragma unroll
        for (int i = 0; i < 4; i++)
            #pragma unroll
            for (int j = 0; j < 4; j++) oacc[i][j] = 0.f;
        #pragma unroll 2
        for (int kk = 0; kk < 18; kk++) {
            int kq = kk * 8 + (lane & 3);
            uint32_t a0 = __float_as_uint(Ps[r0 * PLD + kq]);
            uint32_t a1 = __float_as_uint(Ps[(r0 + 8) * PLD + kq]);
            uint32_t a2 = __float_as_uint(Ps[r0 * PLD + kq + 4]);
            uint32_t a3 = __float_as_uint(Ps[(r0 + 8) * PLD + kq + 4]);
            #pragma unroll
            for (int ni = 0; ni < 4; ni++) {
                int n = nh * 32 + ni * 8 + (lane >> 2);
                uint32_t b0 = f2tf_bits(__float_as_uint(Vs[kq * KVLD + n]));
                uint32_t b1 = f2tf_bits(__float_as_uint(Vs[(kq + 4) * KVLD + n]));
                mma8(oacc[ni], a0, a1, a2, a3, b0, b1);
            }
        }
        #pragma unroll
        for (int ni = 0; ni < 4; ni++) {
            #pragma unroll
            for (int h = 0; h < 2; h++) {
                int row = r0 + h * 8;
                float di = dinv[row];
                int t = b * Q_ + qt * 16 + (row >> 2);
                int head = kv * G_ + (row & 3);
                int col = nh * 32 + ni * 8 + 2 * (lane & 3);
                float2 o;
                o.x = roundtf(oacc[ni][h * 2 + 0] * di);
                o.y = roundtf(oacc[ni][h * 2 + 1] * di);
                *(float2*)&attn[(size_t)t * (NQ_ * HD_) + head * HD_ + col] = o;
            }
        }
    }
}

// ---------------- out reduce ----------------
__global__ void out_reduce(const float* __restrict__ p,
                           const float* __restrict__ hidden,
                           const float* __restrict__ bias,
                           float* __restrict__ out) {
    int t = blockIdx.x, i = threadIdx.x;
    const float4* hh = (const float4*)(hidden + (size_t)t * H_);
    const float4* bb = (const float4*)bias;
    float4 r = hh[i], c = bb[i];
    r.x += c.x; r.y += c.y; r.z += c.z; r.w += c.w;
    #pragma unroll
    for (int s = 0; s < OPJ_SPLIT; s++) {
        float4 a = ((const float4*)(p + (size_t)(s * T_ + t) * H_))[i];
        r.x += a.x; r.y += a.y; r.z += a.z; r.w += a.w;
    }
    ((float4*)(out + (size_t)t * H_))[i] = r;
}

// ---------------- fused rmsnorm2 + router ----------------
__global__ void rms_router(const float* __restrict__ in,
                           const float* __restrict__ w,
                           const float* __restrict__ wr,
                           const float* __restrict__ br,
                           float* __restrict__ x2,
                           int* __restrict__ eidx, float* __restrict__ ewt) {
    int t = blockIdx.x, tid = threadIdx.x;
    const float* x = in + (size_t)t * H_;
    __shared__ float red[256];
    __shared__ float lac[256][E_];
    float ss = 0.f;
    for (int i = tid; i < H_; i += 256) { float v = x[i]; ss += v * v; }
    red[tid] = ss; __syncthreads();
    for (int s = 128; s > 0; s >>= 1) {
        if (tid < s) red[tid] += red[tid + s];
        __syncthreads();
    }
    float r = rsqrtf(red[0] / (float)H_ + EPS_);
    float acc[E_];
    #pragma unroll
    for (int e = 0; e < E_; e++) acc[e] = 0.f;
    for (int i = tid; i < H_; i += 256) {
        float v = x[i] * w[i] * r;
        x2[(size_t)t * H_ + i] = v;
        #pragma unroll
        for (int e = 0; e < E_; e++) acc[e] += v * wr[i * E_ + e];
    }
    #pragma unroll
    for (int e = 0; e < E_; e++) lac[tid][e] = acc[e];
    __syncthreads();
    for (int s = 128; s > 0; s >>= 1) {
        if (tid < s)
            #pragma unroll
            for (int e = 0; e < E_; e++) lac[tid][e] += lac[tid + s][e];
        __syncthreads();
    }
    if (tid == 0) {
        float l[E_];
        #pragma unroll
        for (int e = 0; e < E_; e++) l[e] = lac[0][e] + br[e];
        int i0 = 0; float v0 = l[0];
        #pragma unroll
        for (int e = 1; e < E_; e++) if (l[e] > v0) { v0 = l[e]; i0 = e; }
        int i1 = -1; float v1 = -1e30f;
        #pragma unroll
        for (int e = 0; e < E_; e++)
            if (e != i0 && l[e] > v1) { v1 = l[e]; i1 = e; }
        float e1 = expf(v1 - v0);
        float inv = 1.f / (1.f + e1);
        eidx[t * 2 + 0] = i0; eidx[t * 2 + 1] = i1;
        ewt[t * 2 + 0] = inv; ewt[t * 2 + 1] = e1 * inv;
    }
}

// ---------------- route sort ----------------
__global__ void route_sort_kernel(const int* __restrict__ eidx,
                                  int* __restrict__ eoff, int* __restrict__ ecnt,
                                  int* __restrict__ tokof, int* __restrict__ slotmap) {
    __shared__ int cnt[E_];
    __shared__ int pos[E_];
    int tid = threadIdx.x;
    if (tid < E_) cnt[tid] = 0;
    for (int i = tid; i < NAPAD; i += 256) tokof[i] = -1;
    __syncthreads();
    for (int a = tid; a < T_ * 2; a += 256) atomicAdd(&cnt[eidx[a]], 1);
    __syncthreads();
    if (tid == 0) {
        int off = 0;
        for (int e = 0; e < E_; e++) {
            eoff[e] = off; ecnt[e] = cnt[e]; pos[e] = off;
            off += ((cnt[e] + 127) / 128) * 128;
        }
    }
    __syncthreads();
    for (int a = tid; a < T_ * 2; a += 256) {
        int e = eidx[a];
        int slot = atomicAdd(&pos[e], 1);
        tokof[slot] = a;
        slotmap[a] = slot;
    }
}

// ---------------- gather ----------------
__global__ void gather_kernel(const float* __restrict__ x2,
                              const int* __restrict__ tokof,
                              float* __restrict__ xg) {
    int slot = blockIdx.x;
    int a = tokof[slot];
    float4* dst = (float4*)(xg + (size_t)slot * H_);
    if (a < 0) {
        dst[threadIdx.x] = make_float4(0.f, 0.f, 0.f, 0.f);
    } else {
        float4 v = ((const float4*)(x2 + (size_t)(a >> 1) * H_))[threadIdx.x];
        v.x = roundtf(v.x); v.y = roundtf(v.y);
        v.z = roundtf(v.z); v.w = roundtf(v.w);
        dst[threadIdx.x] = v;
    }
}

// ---------------- combine ----------------
__global__ void combine_kernel(const float* __restrict__ eop,
                               const int* __restrict__ slotmap,
                               const int* __restrict__ eidx,
                               const float* __restrict__ ewt,
                               const float* __restrict__ bd,
                               float* __restrict__ out) {
    int t = blockIdx.x, i = threadIdx.x;
    float4 o = ((float4*)(out + (size_t)t * H_))[i];
    #pragma unroll
    for (int ei = 0; ei < 2; ei++) {
        int s = slotmap[t * 2 + ei];
        int e = eidx[t * 2 + ei];
        float w = ewt[t * 2 + ei];
        float4 a = ((const float4*)(bd + (size_t)e * H_))[i];
        #pragma unroll
        for (int sp = 0; sp < DN_SPLIT; sp++) {
            float4 b = ((const float4*)(eop + (size_t)(sp * NAPAD + s) * H_))[i];
            a.x += b.x; a.y += b.y; a.z += b.z; a.w += b.w;
        }
        o.x += w * a.x; o.y += w * a.y; o.z += w * a.z; o.w += w * a.w;
    }
    ((float4*)(out + (size_t)t * H_))[i] = o;
}

// ---------------- launch ----------------
extern "C" void kernel_launch(void* const* d_in, const int* in_sizes, int n_in,
                              void* d_out, int out_size) {
    const float* hidden = (const float*)d_in[0];
    const float* kvc    = (const float*)d_in[1];
    const int*   pidx   = (const int*)d_in[3];
    const float* sinks  = (const float*)d_in[4];
    const float* w_qkv  = (const float*)d_in[5];
    const float* b_qkv  = (const float*)d_in[6];
    const float* w_o    = (const float*)d_in[7];
    const float* b_o    = (const float*)d_in[8];
    const float* ln1    = (const float*)d_in[9];
    const float* ln2    = (const float*)d_in[10];
    const float* w_r    = (const float*)d_in[11];
    const float* b_r    = (const float*)d_in[12];
    const float* w_gu   = (const float*)d_in[13];
    const float* b_gu   = (const float*)d_in[14];
    const float* w_d    = (const float*)d_in[15];
    const float* b_d    = (const float*)d_in[16];
    float* out = (float*)d_out;

    float *px, *pqkvp, *pattn, *poutp, *px2, *pewt, *pxg, *pact, *peop;
    int *peidx, *peoff, *pecnt, *ptokof, *pslot;
    cudaGetSymbolAddress((void**)&px,     g_x);
    cudaGetSymbolAddress((void**)&pqkvp,  g_qkvp);
    cudaGetSymbolAddress((void**)&pattn,  g_attn);
    cudaGetSymbolAddress((void**)&poutp,  g_outp);
    cudaGetSymbolAddress((void**)&px2,    g_x2);
    cudaGetSymbolAddress((void**)&peidx,  g_eidx);
    cudaGetSymbolAddress((void**)&pewt,   g_ewt);
    cudaGetSymbolAddress((void**)&peoff,  g_eoff);
    cudaGetSymbolAddress((void**)&pecnt,  g_ecnt);
    cudaGetSymbolAddress((void**)&ptokof, g_tokof);
    cudaGetSymbolAddress((void**)&pslot,  g_slotmap);
    cudaGetSymbolAddress((void**)&pxg,    g_xg);
    cudaGetSymbolAddress((void**)&pact,   g_act);
    cudaGetSymbolAddress((void**)&peop,   g_eop);

    cudaFuncSetAttribute(attn_mma,
                         cudaFuncAttributeMaxDynamicSharedMemorySize, ATT_SMEM);
    cudaFuncSetAttribute(gemm_h16<0, QKV_SPLIT>,
                         cudaFuncAttributeMaxDynamicSharedMemorySize, GEMM_SMEM);
    cudaFuncSetAttribute(gemm_h16<0, OPJ_SPLIT>,
                         cudaFuncAttributeMaxDynamicSharedMemorySize, GEMM_SMEM);
    cudaFuncSetAttribute(gemm_h16<2, 1>,
                         cudaFuncAttributeMaxDynamicSharedMemorySize, GEMM_SMEM);
    cudaFuncSetAttribute(gemm_h16<3, DN_SPLIT>,
                         cudaFuncAttributeMaxDynamicSharedMemorySize, GEMM_SMEM);

    rmsnorm_kernel<<<T_, 256>>>(hidden, ln1, px);
    gemm_h16<0, QKV_SPLIT><<<dim3(QKVD / 128, T_ / 128, QKV_SPLIT),
                             256, GEMM_SMEM>>>(
        px, w_qkv, nullptr, pqkvp, H_, QKVD, T_ * QKVD, nullptr, nullptr);
    attn_mma<<<dim3(Q_ / 16, NKV_, B_), 256, ATT_SMEM>>>(
        pqkvp, b_qkv, kvc, pidx, sinks, pattn);
    gemm_h16<0, OPJ_SPLIT><<<dim3(H_ / 128, T_ / 128, OPJ_SPLIT),
                             256, GEMM_SMEM>>>(
        pattn, w_o, nullptr, poutp, H_, H_, T_ * H_, nullptr, nullptr);
    out_reduce<<<T_, 256>>>(poutp, hidden, b_o, out);
    rms_router<<<T_, 256>>>(out, ln2, w_r, b_r, px2, peidx, pewt);
    route_sort_kernel<<<1, 256>>>(peidx, peoff, pecnt, ptokof, pslot);
    gather_kernel<<<NAPAD, 256>>>(px2, ptokof, pxg);
    gemm_h16<2, 1><<<dim3(2 * FFN_ / 128, 8, E_), 256, GEMM_SMEM>>>(
        pxg, w_gu, b_gu, pact, H_, 2 * FFN_, 0, peoff, pecnt);
    gemm_h16<3, DN_SPLIT><<<dim3(H_ / 128, 8, E_ * DN_SPLIT),
                            256, GEMM_SMEM>>>(
        pact, w_d, nullptr, peop, FFN_, H_, NAPAD * H_, peoff, pecnt);
    combine_kernel<<<T_, 256>>>(peop, pslot, peidx, pewt, b_d, out);
}

// round 16
// speedup vs baseline: 1.8556x; 1.1331x over previous
#include <cuda_runtime.h>
#include <cstdint>
#include <math.h>

#define T_    512
#define H_    1024
#define HD_   64
#define NQ_   16
#define NKV_  4
#define G_    4
#define E_    8
#define FFN_  1024
#define B_    4
#define Q_    128
#define P_    8
#define PS_   128
#define S_    1024
#define SW_   128
#define QKVD  1536
#define SCALE_ 0.125f
#define ALPHA_ 1.702f
#define LIMIT_ 7.0f
#define EPS_   1e-5f
#define NAPAD 2048

#define QKV_SPLIT 2
#define OPJ_SPLIT 4
#define DN_SPLIT  2

// ---------------- scratch ----------------
__device__ uint32_t g_xh[T_ * H_ / 2];            // packed half2
__device__ float    g_qkvp[QKV_SPLIT * T_ * QKVD];
__device__ uint32_t g_attnh[T_ * NQ_ * HD_ / 2];  // packed half2
__device__ float    g_outp[OPJ_SPLIT * T_ * H_];
__device__ float    g_x2[T_ * H_];
__device__ int      g_eidx[T_ * 2];
__device__ float    g_ewt[T_ * 2];
__device__ int      g_eoff[E_];
__device__ int      g_ecnt[E_];
__device__ int      g_tokof[NAPAD];
__device__ int      g_slotmap[T_ * 2];
__device__ uint32_t g_xgh[NAPAD * H_ / 2];        // packed half2
__device__ uint32_t g_acth[NAPAD * FFN_ / 2];     // packed half2
__device__ float    g_eop[DN_SPLIT * NAPAD * H_];

// ---------------- helpers ----------------
__device__ __forceinline__ uint32_t f2tf_bits(uint32_t bits) {
    uint32_t r;
    asm("cvt.rna.tf32.f32 %0, %1;" : "=r"(r) : "f"(__uint_as_float(bits)));
    return r;
}
__device__ __forceinline__ float roundtf(float f) {
    uint32_t r;
    asm("cvt.rna.tf32.f32 %0, %1;" : "=r"(r) : "f"(f));
    return __uint_as_float(r);
}
__device__ __forceinline__ uint32_t pack_h2(float lo, float hi) {
    uint32_t r;
    asm("cvt.rn.f16x2.f32 %0, %1, %2;" : "=r"(r) : "f"(hi), "f"(lo));
    return r;
}
__device__ __forceinline__ void mma8(float* c, uint32_t a0, uint32_t a1,
                                     uint32_t a2, uint32_t a3,
                                     uint32_t b0, uint32_t b1) {
    asm volatile("mma.sync.aligned.m16n8k8.row.col.f32.tf32.tf32.f32 "
        "{%0,%1,%2,%3}, {%4,%5,%6,%7}, {%8,%9}, {%0,%1,%2,%3};"
        : "+f"(c[0]), "+f"(c[1]), "+f"(c[2]), "+f"(c[3])
        : "r"(a0), "r"(a1), "r"(a2), "r"(a3), "r"(b0), "r"(b1));
}
__device__ __forceinline__ void mma16(float* c, uint32_t a0, uint32_t a1,
                                      uint32_t a2, uint32_t a3,
                                      uint32_t b0, uint32_t b1) {
    asm volatile("mma.sync.aligned.m16n8k16.row.col.f32.f16.f16.f32 "
        "{%0,%1,%2,%3}, {%4,%5,%6,%7}, {%8,%9}, {%0,%1,%2,%3};"
        : "+f"(c[0]), "+f"(c[1]), "+f"(c[2]), "+f"(c[3])
        : "r"(a0), "r"(a1), "r"(a2), "r"(a3), "r"(b0), "r"(b1));
}
__device__ __forceinline__ void cp16(uint32_t dst, const void* src) {
    asm volatile("cp.async.cg.shared.global [%0], [%1], 16;" :: "r"(dst), "l"(src));
}
#define CP_COMMIT() asm volatile("cp.async.commit_group;")
#define CP_WAIT(n)  asm volatile("cp.async.wait_group %0;" :: "n"(n))

// ---------------- rmsnorm stage 1 (writes packed half2) ----------------
__global__ void rmsnorm_kernel(const float* __restrict__ in,
                               const float* __restrict__ w,
                               uint32_t* __restrict__ outh) {
    int t = blockIdx.x;
    const float* x = in + (size_t)t * H_;
    __shared__ float red[256];
    float ss = 0.f;
    for (int i = threadIdx.x; i < H_; i += 256) { float v = x[i]; ss += v * v; }
    red[threadIdx.x] = ss; __syncthreads();
    for (int s = 128; s > 0; s >>= 1) {
        if (threadIdx.x < s) red[threadIdx.x] += red[threadIdx.x + s];
        __syncthreads();
    }
    float r = rsqrtf(red[0] / (float)H_ + EPS_);
    for (int i = threadIdx.x * 2; i < H_; i += 512) {
        float v0 = x[i] * w[i] * r;
        float v1 = x[i + 1] * w[i + 1] * r;
        outh[((size_t)t * H_ + i) >> 1] = pack_h2(v0, v1);
    }
}

// ------- unified fp16 GEMM (m16n8k16), packed-half A, 4-stage cp.async ------
// MODE 0: raw partial   MODE 2: +bias swiglu -> packed act   MODE 3: raw partial expert
#define ALD2 12
#define BLD 140
#define GEMM_SMEM ((4 * 128 * ALD2 + 4 * 16 * BLD) * 4)
template<int MODE, int SPLIT>
__global__ __launch_bounds__(256) void gemm_h16(
    const uint32_t* __restrict__ A, const float* __restrict__ Bw,
    const float* __restrict__ bias,
    void* __restrict__ Cv, int K, int N, int partStride,
    const int* __restrict__ eoff, const int* __restrict__ ecnt) {
    extern __shared__ uint32_t gsm[];
    uint32_t* Asm = gsm;                    // [4][128][ALD2] packed half2
    float* Bsm = (float*)(gsm + 4 * 128 * ALD2);   // [4][16][BLD]
    int tid = threadIdx.x, lane = tid & 31, wid = tid >> 5;
    int n0 = blockIdx.x * 128;
    int m0, split;
    if (MODE >= 2) {
        int e = blockIdx.z / SPLIT;
        split = blockIdx.z % SPLIT;
        if ((int)blockIdx.y * 128 >= ecnt[e]) return;
        m0 = eoff[e] + blockIdx.y * 128;
        Bw += (size_t)e * K * N;
        if (MODE == 2) bias += (size_t)e * N;
    } else {
        split = blockIdx.z;
        m0 = blockIdx.y * 128;
    }
    int Ksub = K / SPLIT;
    int kbase = split * Ksub;
    int K2 = K >> 1;
    float* C = (float*)Cv;
    C += (size_t)split * partStride;
    uint32_t* Ch = (uint32_t*)Cv;           // MODE 2 packed act output
    int wm = (wid >> 2) * 64, wn = (wid & 3) * 32;

    uint32_t a_base = (uint32_t)__cvta_generic_to_shared(Asm);
    uint32_t b_base = (uint32_t)__cvta_generic_to_shared(Bsm);
    int arow0 = tid >> 1, ah0 = (tid & 1) * 4;   // A: 8 uint32/row, 2 thr/row
    int brow0 = tid >> 4, bc0 = tid & 15;

    float acc[16][4];
    #pragma unroll
    for (int i = 0; i < 16; i++)
        #pragma unroll
        for (int j = 0; j < 4; j++) acc[i][j] = 0.f;

    int nchunks = Ksub / 16;
    auto issue = [&](int c, int s) {
        int k0 = kbase + c * 16;
        cp16(a_base + (((s * 128 + arow0) * ALD2) + ah0) * 4,
             &A[(size_t)(m0 + arow0) * K2 + (k0 >> 1) + ah0]);
        #pragma unroll
        for (int l = 0; l < 2; l++) {
            int cc = bc0 * 2 + l;
            cp16(b_base + (((s * 16 + brow0) * BLD) + cc * 4) * 4,
                 &Bw[(size_t)(k0 + brow0) * N + n0 + cc * 4]);
        }
        CP_COMMIT();
    };

    int g = lane >> 2, q4 = lane & 3;
    int kq = q4 * 2;
    issue(0, 0); issue(1, 1); issue(2, 2);
    for (int c = 0; c < nchunks; c++) {
        CP_WAIT(2);
        __syncthreads();
        if (c + 3 < nchunks) issue(c + 3, (c + 3) & 3); else CP_COMMIT();
        int s = c & 3;
        const uint32_t* Ab = Asm + s * 128 * ALD2;
        const float* Bb = Bsm + s * 16 * BLD;
        uint32_t bf[4][2];
        #pragma unroll
        for (int ni = 0; ni < 4; ni++) {
            int n = wn + ni * 8 + g;
            bf[ni][0] = pack_h2(Bb[kq * BLD + n], Bb[(kq + 1) * BLD + n]);
            bf[ni][1] = pack_h2(Bb[(kq + 8) * BLD + n], Bb[(kq + 9) * BLD + n]);
        }
        #pragma unroll
        for (int mi = 0; mi < 4; mi++) {
            int m = wm + mi * 16 + g;
            uint32_t a0 = Ab[m * ALD2 + q4];
            uint32_t a1 = Ab[(m + 8) * ALD2 + q4];
            uint32_t a2 = Ab[m * ALD2 + q4 + 4];
            uint32_t a3 = Ab[(m + 8) * ALD2 + q4 + 4];
            #pragma unroll
            for (int ni = 0; ni < 4; ni++)
                mma16(acc[mi * 4 + ni], a0, a1, a2, a3, bf[ni][0], bf[ni][1]);
        }
        __syncthreads();
    }
    #pragma unroll
    for (int mi = 0; mi < 4; mi++) {
        #pragma unroll
        for (int ni = 0; ni < 4; ni++) {
            float* cc = acc[mi * 4 + ni];
            int row = m0 + wm + mi * 16 + g;
            int col = n0 + wn + ni * 8 + 2 * q4;
            #pragma unroll
            for (int h = 0; h < 2; h++) {
                int r = row + h * 8;
                float v0 = cc[h * 2 + 0];
                float v1 = cc[h * 2 + 1];
                if (MODE == 2) {
                    float gg = fminf(v0 + bias[col], LIMIT_);
                    float u = fminf(fmaxf(v1 + bias[col + 1], -LIMIT_), LIMIT_);
                    float glu = gg / (1.f + expf(-gg * ALPHA_));
                    float av = (u + 1.f) * glu;
                    float partner = __shfl_xor_sync(0xffffffffu, av, 1);
                    if ((lane & 1) == 0) {
                        int f = col >> 1;      // even here
                        Ch[(size_t)r * (FFN_ / 2) + (f >> 1)] = pack_h2(av, partner);
                    }
                } else {
                    *(float2*)&C[(size_t)r * N + col] = make_float2(v0, v1);
                }
            }
        }
    }
}

// ---------------- tensor-core sliding-window attention (2 qkv partials) ------
#define QLD 68
#define KVLD 72
#define PLD 148
#define ATT_SMEM ((64 * QLD + 2 * 144 * KVLD + 64 * PLD + 64) * 4)
__global__ void attn_mma(const float* __restrict__ qkvp,
                         const float* __restrict__ bqkv,
                         const float* __restrict__ kvc,
                         const int* __restrict__ pidx,
                         const float* __restrict__ sinks,
                         uint32_t* __restrict__ attnh) {
    extern __shared__ float sm[];
    float* Qs = sm;
    float* Ks = Qs + 64 * QLD;
    float* Vs = Ks + 144 * KVLD;
    float* Ps = Vs + 144 * KVLD;
    float* dinv = Ps + 64 * PLD;
    int qt = blockIdx.x, kv = blockIdx.y, b = blockIdx.z;
    int tid = threadIdx.x, lane = tid & 31, wid = tid >> 5;
    int qpos0 = S_ - Q_ + qt * 16;
    int base = qpos0 - (SW_ - 1);

    #pragma unroll
    for (int l = 0; l < 4; l++) {
        int f = tid + 256 * l;
        int r = f >> 4, d4 = f & 15;
        int ql = r >> 2, g = r & 3;
        size_t o = (size_t)(b * Q_ + qt * 16 + ql) * QKVD + (kv * G_ + g) * HD_ + d4 * 4;
        float4 acc = *(const float4*)&bqkv[(kv * G_ + g) * HD_ + d4 * 4];
        #pragma unroll
        for (int j = 0; j < QKV_SPLIT; j++) {
            float4 a = *(const float4*)&qkvp[(size_t)j * T_ * QKVD + o];
            acc.x += a.x; acc.y += a.y; acc.z += a.z; acc.w += a.w;
        }
        Qs[r * QLD + d4 * 4 + 0] = roundtf(acc.x * SCALE_);
        Qs[r * QLD + d4 * 4 + 1] = roundtf(acc.y * SCALE_);
        Qs[r * QLD + d4 * 4 + 2] = roundtf(acc.z * SCALE_);
        Qs[r * QLD + d4 * 4 + 3] = roundtf(acc.w * SCALE_);
    }
    for (int f = tid; f < 143 * 16; f += 256) {
        int k = f >> 4, d4 = f & 15;
        int kpos = base + k;
        float4 kf, vf;
        if (kpos < S_ - Q_) {
            int page = pidx[b * P_ + (kpos >> 7)];
            size_t o = (((size_t)page * 2) * PS_ + (kpos & 127)) * NKV_ + kv;
            kf = *(const float4*)&kvc[o * HD_ + d4 * 4];
            vf = *(const float4*)&kvc[(o + (size_t)PS_ * NKV_) * HD_ + d4 * 4];
        } else {
            size_t t = (size_t)(b * Q_ + kpos - (S_ - Q_)) * QKVD;
            int ck = NQ_ * HD_ + kv * HD_ + d4 * 4;
            int cv = (NQ_ + NKV_) * HD_ + kv * HD_ + d4 * 4;
            kf = *(const float4*)&bqkv[ck];
            vf = *(const float4*)&bqkv[cv];
            #pragma unroll
            for (int j = 0; j < QKV_SPLIT; j++) {
                float4 a = *(const float4*)&qkvp[(size_t)j * T_ * QKVD + t + ck];
                kf.x += a.x; kf.y += a.y; kf.z += a.z; kf.w += a.w;
                float4 c = *(const float4*)&qkvp[(size_t)j * T_ * QKVD + t + cv];
                vf.x += c.x; vf.y += c.y; vf.z += c.z; vf.w += c.w;
            }
        }
        *(float4*)&Ks[k * KVLD + d4 * 4] = kf;
        *(float4*)&Vs[k * KVLD + d4 * 4] = vf;
    }
    if (tid < 32) {
        int d4 = tid & 15;
        if (tid < 16) *(float4*)&Ks[143 * KVLD + d4 * 4] = make_float4(0, 0, 0, 0);
        else          *(float4*)&Vs[143 * KVLD + d4 * 4] = make_float4(0, 0, 0, 0);
    }
    __syncthreads();

    int mt = wid & 3, nh = wid >> 2;
    int r0 = mt * 16 + (lane >> 2);
    {
        float sacc[9][4];
        #pragma unroll
        for (int i = 0; i < 9; i++)
            #pragma unroll
            for (int j = 0; j < 4; j++) sacc[i][j] = 0.f;
        #pragma unroll
        for (int kk = 0; kk < 8; kk++) {
            int kq = kk * 8 + (lane & 3);
            uint32_t a0 = __float_as_uint(Qs[r0 * QLD + kq]);
            uint32_t a1 = __float_as_uint(Qs[(r0 + 8) * QLD + kq]);
            uint32_t a2 = __float_as_uint(Qs[r0 * QLD + kq + 4]);
            uint32_t a3 = __float_as_uint(Qs[(r0 + 8) * QLD + kq + 4]);
            #pragma unroll
            for (int ni = 0; ni < 9; ni++) {
                int n = nh * 72 + ni * 8 + (lane >> 2);
                uint32_t b0 = f2tf_bits(__float_as_uint(Ks[n * KVLD + kq]));
                uint32_t b1 = f2tf_bits(__float_as_uint(Ks[n * KVLD + kq + 4]));
                mma8(sacc[ni], a0, a1, a2, a3, b0, b1);
            }
        }
        #pragma unroll
        for (int ni = 0; ni < 9; ni++) {
            #pragma unroll
            for (int h = 0; h < 2; h++) {
                int row = r0 + h * 8;
                int ql = row >> 2;
                int cb = nh * 72 + ni * 8 + 2 * (lane & 3);
                float v0 = sacc[ni][h * 2 + 0];
                float v1 = sacc[ni][h * 2 + 1];
                if (cb < ql || cb > ql + 127) v0 = -1e30f;
                if (cb + 1 < ql || cb + 1 > ql + 127) v1 = -1e30f;
                Ps[row * PLD + cb] = v0;
                Ps[row * PLD + cb + 1] = v1;
            }
        }
    }
    __syncthreads();
    {
        int row = tid >> 2, part = tid & 3;
        float mx = -1e30f;
        #pragma unroll 4
        for (int j = 0; j < 36; j++)
            mx = fmaxf(mx, Ps[row * PLD + part * 36 + j]);
        mx = fmaxf(mx, __shfl_xor_sync(0xffffffffu, mx, 1));
        mx = fmaxf(mx, __shfl_xor_sync(0xffffffffu, mx, 2));
        float sum = 0.f;
        #pragma unroll 4
        for (int j = 0; j < 36; j++) {
            float p = expf(Ps[row * PLD + part * 36 + j] - mx);
            Ps[row * PLD + part * 36 + j] = roundtf(p);
            sum += p;
        }
        sum += __shfl_xor_sync(0xffffffffu, sum, 1);
        sum += __shfl_xor_sync(0xffffffffu, sum, 2);
        if (part == 0)
            dinv[row] = 1.f / (sum + expf(sinks[kv * G_ + (row & 3)] - mx));
    }
    __syncthreads();
    {
        float oacc[4][4];
        #pragma unroll
        for (int i = 0; i < 4; i++)
            #pragma unroll
            for (int j = 0; j < 4; j++) oacc[i][j] = 0.f;
        #pragma unroll 2
        for (int kk = 0; kk < 18; kk++) {
            int kq = kk * 8 + (lane & 3);
            uint32_t a0 = __float_as_uint(Ps[r0 * PLD + kq]);
            uint32_t a1 = __float_as_uint(Ps[(r0 + 8) * PLD + kq]);
            uint32_t a2 = __float_as_uint(Ps[r0 * PLD + kq + 4]);
            uint32_t a3 = __float_as_uint(Ps[(r0 + 8) * PLD + kq + 4]);
            #pragma unroll
            for (int ni = 0; ni < 4; ni++) {
                int n = nh * 32 + ni * 8 + (lane >> 2);
                uint32_t b0 = f2tf_bits(__float_as_uint(Vs[kq * KVLD + n]));
                uint32_t b1 = f2tf_bits(__float_as_uint(Vs[(kq + 4) * KVLD + n]));
                mma8(oacc[ni], a0, a1, a2, a3, b0, b1);
            }
        }
        #pragma unroll
        for (int ni = 0; ni < 4; ni++) {
            #pragma unroll
            for (int h = 0; h < 2; h++) {
                int row = r0 + h * 8;
                float di = dinv[row];
                int t = b * Q_ + qt * 16 + (row >> 2);
                int head = kv * G_ + (row & 3);
                int col = nh * 32 + ni * 8 + 2 * (lane & 3);
                attnh[((size_t)t * (NQ_ * HD_) + head * HD_ + col) >> 1] =
                    pack_h2(oacc[ni][h * 2 + 0] * di, oacc[ni][h * 2 + 1] * di);
            }
        }
    }
}

// ---------------- out reduce ----------------
__global__ void out_reduce(const float* __restrict__ p,
                           const float* __restrict__ hidden,
                           const float* __restrict__ bias,
                           float* __restrict__ out) {
    int t = blockIdx.x, i = threadIdx.x;
    const float4* hh = (const float4*)(hidden + (size_t)t * H_);
    const float4* bb = (const float4*)bias;
    float4 r = hh[i], c = bb[i];
    r.x += c.x; r.y += c.y; r.z += c.z; r.w += c.w;
    #pragma unroll
    for (int s = 0; s < OPJ_SPLIT; s++) {
        float4 a = ((const float4*)(p + (size_t)(s * T_ + t) * H_))[i];
        r.x += a.x; r.y += a.y; r.z += a.z; r.w += a.w;
    }
    ((float4*)(out + (size_t)t * H_))[i] = r;
}

// ---------------- fused rmsnorm2 + router ----------------
__global__ void rms_router(const float* __restrict__ in,
                           const float* __restrict__ w,
                           const float* __restrict__ wr,
                           const float* __restrict__ br,
                           float* __restrict__ x2,
                           int* __restrict__ eidx, float* __restrict__ ewt) {
    int t = blockIdx.x, tid = threadIdx.x;
    const float* x = in + (size_t)t * H_;
    __shared__ float red[256];
    __shared__ float lac[256][E_];
    float ss = 0.f;
    for (int i = tid; i < H_; i += 256) { float v = x[i]; ss += v * v; }
    red[tid] = ss; __syncthreads();
    for (int s = 128; s > 0; s >>= 1) {
        if (tid < s) red[tid] += red[tid + s];
        __syncthreads();
    }
    float r = rsqrtf(red[0] / (float)H_ + EPS_);
    float acc[E_];
    #pragma unroll
    for (int e = 0; e < E_; e++) acc[e] = 0.f;
    for (int i = tid; i < H_; i += 256) {
        float v = x[i] * w[i] * r;
        x2[(size_t)t * H_ + i] = v;
        #pragma unroll
        for (int e = 0; e < E_; e++) acc[e] += v * wr[i * E_ + e];
    }
    #pragma unroll
    for (int e = 0; e < E_; e++) lac[tid][e] = acc[e];
    __syncthreads();
    for (int s = 128; s > 0; s >>= 1) {
        if (tid < s)
            #pragma unroll
            for (int e = 0; e < E_; e++) lac[tid][e] += lac[tid + s][e];
        __syncthreads();
    }
    if (tid == 0) {
        float l[E_];
        #pragma unroll
        for (int e = 0; e < E_; e++) l[e] = lac[0][e] + br[e];
        int i0 = 0; float v0 = l[0];
        #pragma unroll
        for (int e = 1; e < E_; e++) if (l[e] > v0) { v0 = l[e]; i0 = e; }
        int i1 = -1; float v1 = -1e30f;
        #pragma unroll
        for (int e = 0; e < E_; e++)
            if (e != i0 && l[e] > v1) { v1 = l[e]; i1 = e; }
        float e1 = expf(v1 - v0);
        float inv = 1.f / (1.f + e1);
        eidx[t * 2 + 0] = i0; eidx[t * 2 + 1] = i1;
        ewt[t * 2 + 0] = inv; ewt[t * 2 + 1] = e1 * inv;
    }
}

// ---------------- route sort ----------------
__global__ void route_sort_kernel(const int* __restrict__ eidx,
                                  int* __restrict__ eoff, int* __restrict__ ecnt,
                                  int* __restrict__ tokof, int* __restrict__ slotmap) {
    __shared__ int cnt[E_];
    __shared__ int pos[E_];
    int tid = threadIdx.x;
    if (tid < E_) cnt[tid] = 0;
    for (int i = tid; i < NAPAD; i += 256) tokof[i] = -1;
    __syncthreads();
    for (int a = tid; a < T_ * 2; a += 256) atomicAdd(&cnt[eidx[a]], 1);
    __syncthreads();
    if (tid == 0) {
        int off = 0;
        for (int e = 0; e < E_; e++) {
            eoff[e] = off; ecnt[e] = cnt[e]; pos[e] = off;
            off += ((cnt[e] + 127) / 128) * 128;
        }
    }
    __syncthreads();
    for (int a = tid; a < T_ * 2; a += 256) {
        int e = eidx[a];
        int slot = atomicAdd(&pos[e], 1);
        tokof[slot] = a;
        slotmap[a] = slot;
    }
}

// ---------------- gather (packs half2) ----------------
__global__ void gather_kernel(const float* __restrict__ x2,
                              const int* __restrict__ tokof,
                              uint32_t* __restrict__ xgh) {
    int slot = blockIdx.x;
    int a = tokof[slot];
    uint2* dst = (uint2*)(xgh + (size_t)slot * (H_ / 2));
    if (a < 0) {
        dst[threadIdx.x] = make_uint2(0u, 0u);
    } else {
        float4 v = ((const float4*)(x2 + (size_t)(a >> 1) * H_))[threadIdx.x];
        dst[threadIdx.x] = make_uint2(pack_h2(v.x, v.y), pack_h2(v.z, v.w));
    }
}

// ---------------- combine ----------------
__global__ void combine_kernel(const float* __restrict__ eop,
                               const int* __restrict__ slotmap,
                               const int* __restrict__ eidx,
                               const float* __restrict__ ewt,
                               const float* __restrict__ bd,
                               float* __restrict__ out) {
    int t = blockIdx.x, i = threadIdx.x;
    float4 o = ((float4*)(out + (size_t)t * H_))[i];
    #pragma unroll
    for (int ei = 0; ei < 2; ei++) {
        int s = slotmap[t * 2 + ei];
        int e = eidx[t * 2 + ei];
        float w = ewt[t * 2 + ei];
        float4 a = ((const float4*)(bd + (size_t)e * H_))[i];
        #pragma unroll
        for (int sp = 0; sp < DN_SPLIT; sp++) {
            float4 b = ((const float4*)(eop + (size_t)(sp * NAPAD + s) * H_))[i];
            a.x += b.x; a.y += b.y; a.z += b.z; a.w += b.w;
        }
        o.x += w * a.x; o.y += w * a.y; o.z += w * a.z; o.w += w * a.w;
    }
    ((float4*)(out + (size_t)t * H_))[i] = o;
}

// ---------------- launch ----------------
extern "C" void kernel_launch(void* const* d_in, const int* in_sizes, int n_in,
                              void* d_out, int out_size) {
    const float* hidden = (const float*)d_in[0];
    const float* kvc    = (const float*)d_in[1];
    const int*   pidx   = (const int*)d_in[3];
    const float* sinks  = (const float*)d_in[4];
    const float* w_qkv  = (const float*)d_in[5];
    const float* b_qkv  = (const float*)d_in[6];
    const float* w_o    = (const float*)d_in[7];
    const float* b_o    = (const float*)d_in[8];
    const float* ln1    = (const float*)d_in[9];
    const float* ln2    = (const float*)d_in[10];
    const float* w_r    = (const float*)d_in[11];
    const float* b_r    = (const float*)d_in[12];
    const float* w_gu   = (const float*)d_in[13];
    const float* b_gu   = (const float*)d_in[14];
    const float* w_d    = (const float*)d_in[15];
    const float* b_d    = (const float*)d_in[16];
    float* out = (float*)d_out;

    float *pqkvp, *poutp, *px2, *pewt, *peop;
    uint32_t *pxh, *pattnh, *pxgh, *pacth;
    int *peidx, *peoff, *pecnt, *ptokof, *pslot;
    cudaGetSymbolAddress((void**)&pxh,    g_xh);
    cudaGetSymbolAddress((void**)&pqkvp,  g_qkvp);
    cudaGetSymbolAddress((void**)&pattnh, g_attnh);
    cudaGetSymbolAddress((void**)&poutp,  g_outp);
    cudaGetSymbolAddress((void**)&px2,    g_x2);
    cudaGetSymbolAddress((void**)&peidx,  g_eidx);
    cudaGetSymbolAddress((void**)&pewt,   g_ewt);
    cudaGetSymbolAddress((void**)&peoff,  g_eoff);
    cudaGetSymbolAddress((void**)&pecnt,  g_ecnt);
    cudaGetSymbolAddress((void**)&ptokof, g_tokof);
    cudaGetSymbolAddress((void**)&pslot,  g_slotmap);
    cudaGetSymbolAddress((void**)&pxgh,   g_xgh);
    cudaGetSymbolAddress((void**)&pacth,  g_acth);
    cudaGetSymbolAddress((void**)&peop,   g_eop);

    cudaFuncSetAttribute(attn_mma,
                         cudaFuncAttributeMaxDynamicSharedMemorySize, ATT_SMEM);
    cudaFuncSetAttribute(gemm_h16<0, QKV_SPLIT>,
                         cudaFuncAttributeMaxDynamicSharedMemorySize, GEMM_SMEM);
    cudaFuncSetAttribute(gemm_h16<0, OPJ_SPLIT>,
                         cudaFuncAttributeMaxDynamicSharedMemorySize, GEMM_SMEM);
    cudaFuncSetAttribute(gemm_h16<2, 1>,
                         cudaFuncAttributeMaxDynamicSharedMemorySize, GEMM_SMEM);
    cudaFuncSetAttribute(gemm_h16<3, DN_SPLIT>,
                         cudaFuncAttributeMaxDynamicSharedMemorySize, GEMM_SMEM);

    rmsnorm_kernel<<<T_, 256>>>(hidden, ln1, pxh);
    gemm_h16<0, QKV_SPLIT><<<dim3(QKVD / 128, T_ / 128, QKV_SPLIT),
                             256, GEMM_SMEM>>>(
        pxh, w_qkv, nullptr, pqkvp, H_, QKVD, T_ * QKVD, nullptr, nullptr);
    attn_mma<<<dim3(Q_ / 16, NKV_, B_), 256, ATT_SMEM>>>(
        pqkvp, b_qkv, kvc, pidx, sinks, pattnh);
    gemm_h16<0, OPJ_SPLIT><<<dim3(H_ / 128, T_ / 128, OPJ_SPLIT),
                             256, GEMM_SMEM>>>(
        pattnh, w_o, nullptr, poutp, H_, H_, T_ * H_, nullptr, nullptr);
    out_reduce<<<T_, 256>>>(poutp, hidden, b_o, out);
    rms_router<<<T_, 256>>>(out, ln2, w_r, b_r, px2, peidx, pewt);
    route_sort_kernel<<<1, 256>>>(peidx, peoff, pecnt, ptokof, pslot);
    gather_kernel<<<NAPAD, 256>>>(px2, ptokof, pxgh);
    gemm_h16<2, 1><<<dim3(2 * FFN_ / 128, 8, E_), 256, GEMM_SMEM>>>(
        pxgh, w_gu, b_gu, pacth, H_, 2 * FFN_, 0, peoff, pecnt);
    gemm_h16<3, DN_SPLIT><<<dim3(H_ / 128, 8, E_ * DN_SPLIT),
                            256, GEMM_SMEM>>>(
        pacth, w_d, nullptr, peop, FFN_, H_, NAPAD * H_, peoff, pecnt);
    combine_kernel<<<T_, 256>>>(peop, pslot, peidx, pewt, b_d, out);
}